// round 8
// baseline (speedup 1.0000x reference)
#include <cuda_runtime.h>
#include <cstdint>

#define NMAX 8192
#define HDIM 128
#define RPB 32      // rows per gemm block
#define CHUNK 2048  // sort chunk per block
#define CHUNKS 64   // hub-partial chunks (R4-exact)

// ============================================================================
// Device scratch
// ============================================================================
__device__ int   g_edges[2][NMAX * 5];
__device__ float g_y[NMAX * HDIM];
__device__ float g_hA[NMAX * HDIM];
__device__ float g_hB[NMAX * HDIM];
__device__ float g_xs[2][NMAX * HDIM];
__device__ int   g_perm[2][NMAX];
__device__ int   g_indeg[NMAX];
__device__ float g_dinv[NMAX];
__device__ float g_z[NMAX];
__device__ float g_score[NMAX];
__device__ unsigned long long g_keys[NMAX];
__device__ int   g_idx[NMAX];
__device__ float g_sv[NMAX];
__device__ int   g_newid[NMAX];
__device__ int   g_hubs[5];
__device__ int   g_nhubs;
__device__ float g_part[CHUNKS * 5 * HDIM];
__device__ unsigned char g_mask[NMAX];
__device__ unsigned g_rmax[3][HDIM];
__device__ float g_rsum[3][HDIM];

// ============================================================================
// Helpers
// ============================================================================
__device__ __forceinline__ unsigned ordf(float v) {
    unsigned u = __float_as_uint(v);
    return (u & 0x80000000u) ? ~u : (u | 0x80000000u);
}
__device__ __forceinline__ float deco(unsigned e) {
    unsigned u = (e & 0x80000000u) ? (e & 0x7fffffffu) : ~e;
    return __uint_as_float(u);
}

// ============================================================================
// Init: degenerate stage-0 edges (eye*inf NaN semantics), closed-form indeg,
// zero readout accumulators.
// ============================================================================
__global__ void init_kernel(int* __restrict__ eout, int* __restrict__ indeg) {
    int i = blockIdx.x * 256 + threadIdx.x;
    if (i < NMAX) {
        int pos = 0;
        #pragma unroll
        for (int j = 0; j < 5; j++)
            if (j != i && pos < 4) eout[i * 5 + (pos++)] = j;
        eout[i * 5 + 4] = -1;
        indeg[i] = (i < 4) ? (NMAX - 1) : ((i == 4) ? 4 : 0);
    }
    if (i < 3 * HDIM) {
        (&g_rmax[0][0])[i] = 0u;
        (&g_rsum[0][0])[i] = 0.f;
    }
}

// ============================================================================
// dinv + hub detection (1 block) — dinv expression identical to R4
// ============================================================================
__global__ void dinvhubs_kernel(const int* __restrict__ indeg,
                                float* __restrict__ dinv, int n) {
    __shared__ int cnt;
    __shared__ int sl[16];
    int t = threadIdx.x;
    if (t == 0) cnt = 0;
    __syncthreads();
    for (int i = t; i < n; i += 1024) {
        int d = indeg[i];
        float deg = 1.f + (float)d;
        dinv[i] = 1.0f / sqrtf(deg);
        if (d > 0) {
            int p = atomicAdd(&cnt, 1);
            if (p < 16) sl[p] = i;
        }
    }
    __syncthreads();
    if (t == 0) {
        int m = cnt < 5 ? cnt : 5;
        for (int i = 1; i < m; i++) {
            int v = sl[i], j = i - 1;
            while (j >= 0 && sl[j] > v) { sl[j + 1] = sl[j]; j--; }
            sl[j + 1] = v;
        }
        g_nhubs = m;
        #pragma unroll
        for (int k = 0; k < 5; k++) g_hubs[k] = (k < m) ? sl[k] : -1;
    }
}

// ============================================================================
// Fused GEMM + base hA + mask epilogue.
// y = h@W (32 rows/block): ascending-k fmaf chains (bit == R4), W preloaded
// 8 at a time for MLP. hA = relu(dinv^2*y + b) (bit == R4).
// Threads c<32 compute the hub mask for their row (same boolean as R4).
// ============================================================================
__global__ void gemmF_kernel(const float* __restrict__ h, const float* __restrict__ W,
                             const float* __restrict__ b, const float* __restrict__ dinv,
                             const int* __restrict__ edges,
                             float* __restrict__ y, float* __restrict__ hA,
                             unsigned char* __restrict__ mask) {
    __shared__ float hs[RPB][HDIM];
    __shared__ float sdi[RPB];
    __shared__ int shub[5];
    const int c = threadIdx.x;
    const int r0 = blockIdx.x * RPB;
    if (c < 5) shub[c] = g_hubs[c];
    if (c < RPB) sdi[c] = dinv[r0 + c];
    #pragma unroll
    for (int r = 0; r < RPB; r++) hs[r][c] = h[(size_t)(r0 + r) * HDIM + c];
    __syncthreads();

    float acc[RPB];
    #pragma unroll
    for (int r = 0; r < RPB; r++) acc[r] = 0.f;
    #pragma unroll
    for (int k0 = 0; k0 < HDIM; k0 += 8) {
        float wv[8];
        #pragma unroll
        for (int q = 0; q < 8; q++) wv[q] = W[(k0 + q) * HDIM + c];
        #pragma unroll
        for (int q = 0; q < 8; q++) {
            #pragma unroll
            for (int r = 0; r < RPB; r++) acc[r] = fmaf(hs[r][k0 + q], wv[q], acc[r]);
        }
    }
    float bc = b[c];
    #pragma unroll
    for (int r = 0; r < RPB; r++) {
        y[(size_t)(r0 + r) * HDIM + c] = acc[r];
        float dc = sdi[r];
        float v = fmaf(dc * dc, acc[r], bc);
        hA[(size_t)(r0 + r) * HDIM + c] = fmaxf(v, 0.f);
    }

    // mask epilogue (identical boolean to R4 inline test)
    if (c < RPB) {
        int r = r0 + c;
        int e0 = edges[r * 5 + 0], e1 = edges[r * 5 + 1], e2 = edges[r * 5 + 2];
        int e3 = edges[r * 5 + 3], e4 = edges[r * 5 + 4];
        unsigned m = 0;
        #pragma unroll
        for (int k = 0; k < 5; k++) {
            int hv = shub[k];
            bool hit = (hv >= 0) &&
                       (e0 == hv || e1 == hv || e2 == hv || e3 == hv || e4 == hv || r == hv);
            if (hit) m |= 1u << k;
        }
        mask[r] = (unsigned char)m;
    }
}

// ============================================================================
// Hub partials: 64 chunks, ascending rows, fadd chain (R4 bits).
// 16-wide batched loads (MLP=16); chain order unchanged.
// ============================================================================
__global__ void hubpartF_kernel(const float* __restrict__ y, const float* __restrict__ dinv,
                                const unsigned char* __restrict__ mask,
                                float* __restrict__ part, int n) {
    int f = threadIdx.x;
    int ch = blockIdx.x;
    int rpc = n >> 6;   // 128/64/32, divisible by 16
    float acc[5] = {0.f, 0.f, 0.f, 0.f, 0.f};
    int rbeg = ch * rpc;
    for (int rb = rbeg; rb < rbeg + rpc; rb += 16) {
        float wv[16];
        unsigned mm[16];
        #pragma unroll
        for (int q = 0; q < 16; q++) {
            mm[q] = mask[rb + q];
            wv[q] = dinv[rb + q] * y[(size_t)(rb + q) * HDIM + f];
        }
        #pragma unroll
        for (int q = 0; q < 16; q++) {
            #pragma unroll
            for (int k = 0; k < 5; k++)
                if ((mm[q] >> k) & 1u) acc[k] += wv[q];
        }
    }
    #pragma unroll
    for (int k = 0; k < 5; k++) part[(ch * 5 + k) * HDIM + f] = acc[k];
}

// ============================================================================
// z + base score + key (fused; bits == R4). Hub rows produce garbage here;
// hubfix2 overwrites z/score/keys for hubs afterwards.
// ============================================================================
__global__ void zdotSK_kernel(const float* __restrict__ h, const float* __restrict__ Wp,
                              const float* __restrict__ dinv, const float* __restrict__ bp,
                              float* __restrict__ z, float* __restrict__ score,
                              unsigned long long* __restrict__ keys, int n) {
    int w = threadIdx.x >> 5, lane = threadIdx.x & 31;
    int r = blockIdx.x * 8 + w;
    if (r >= n) return;
    float s = 0.f;
    #pragma unroll
    for (int kk = lane; kk < HDIM; kk += 32)
        s = fmaf(h[(size_t)r * HDIM + kk], Wp[kk], s);
    #pragma unroll
    for (int o = 16; o > 0; o >>= 1) s += __shfl_down_sync(0xffffffffu, s, o);
    if (lane == 0) {
        z[r] = s;
        float dc = dinv[r];
        float sc = fmaf(dc * dc, s, bp[0]);
        score[r] = sc;
        keys[r] = ((unsigned long long)(~ordf(sc)) << 32) | (unsigned)r;
    }
}

// ============================================================================
// Merged hub fixup (1 block, 256 threads):
//  1) chunk-reduce partials (ascending, R4 bits) -> hub hA rows
//  2) hub z via the SAME warp-strided fmaf chain + shfl tree as zdot (bit-exact)
//  3) hub scores via R4-verbatim 256-thread strided sum + tree
//  4) hub keys
// ============================================================================
__global__ void hubfix2_kernel(const float* __restrict__ part,
                               const float* __restrict__ dinv, const float* __restrict__ b,
                               const float* __restrict__ Wp, const float* __restrict__ bp,
                               const unsigned char* __restrict__ mask,
                               float* __restrict__ hA, float* __restrict__ z,
                               float* __restrict__ score,
                               unsigned long long* __restrict__ keys, int n) {
    __shared__ float hv[5][HDIM];
    __shared__ float sWp[HDIM];
    __shared__ int shub[5];
    __shared__ int snh;
    __shared__ float red[256];
    int t = threadIdx.x;
    if (t < 5) shub[t] = g_hubs[t];
    if (t == 0) snh = g_nhubs;
    if (t < HDIM) sWp[t] = Wp[t];
    __syncthreads();
    int nh = snh;

    // phase 1: chunk reduce (R4-verbatim order) -> hub hA rows
    if (t < HDIM) {
        int f = t;
        for (int k = 0; k < nh; k++) {
            float S = 0.f;
            for (int ch = 0; ch < CHUNKS; ch++) S += part[(ch * 5 + k) * HDIM + f];
            int c = shub[k];
            float v = fmaf(dinv[c], S, b[f]);
            v = fmaxf(v, 0.f);
            hA[(size_t)c * HDIM + f] = v;
            hv[k][f] = v;
        }
    }
    __syncthreads();

    // phase 2: hub z, exact zdot bit pattern (warp per hub)
    {
        int w = t >> 5, lane = t & 31;
        if (w < nh) {
            float s = 0.f;
            #pragma unroll
            for (int kk = 0; kk < 4; kk++)
                s = fmaf(hv[w][lane + 32 * kk], sWp[lane + 32 * kk], s);
            #pragma unroll
            for (int o = 16; o > 0; o >>= 1) s += __shfl_down_sync(0xffffffffu, s, o);
            if (lane == 0) z[shub[w]] = s;
        }
    }
    __syncthreads();   // gmem z writes visible block-wide

    // phases 3+4: per hub, R4-verbatim 256-thread strided sum + tree
    for (int k = 0; k < nh; k++) {
        int hub = shub[k];
        float p = 0.f;
        for (int r = t; r < n; r += 256) {
            if (t < 256 && ((mask[r] >> k) & 1u)) p += dinv[r] * z[r];
        }
        if (t < 256) red[t] = p;
        __syncthreads();
        for (int o = 128; o > 0; o >>= 1) {
            if (t < o) red[t] += red[t + o];
            __syncthreads();
        }
        if (t == 0) {
            float sc = fmaf(dinv[hub], red[0], bp[0]);
            score[hub] = sc;
            keys[hub] = ((unsigned long long)(~ordf(sc)) << 32) | (unsigned)hub;
        }
        __syncthreads();
    }
}

// ============================================================================
// Multi-block bitonic sort (+ fused extract on the final pass)
// ============================================================================
__device__ __forceinline__ void do_extract2(const unsigned long long* sk, int g0, int t,
                                            const float* __restrict__ score,
                                            int* __restrict__ idx, float* __restrict__ sv,
                                            int* __restrict__ newid, int* __restrict__ indeg,
                                            int ksel) {
    #pragma unroll
    for (int h = 0; h < 2; h++) {
        int li = t + h * 1024;
        int i = g0 + li;
        int id = (int)(sk[li] & 0xffffffffull);
        newid[id] = (i < ksel) ? i : -1;
        if (i < ksel) {
            idx[i] = id;
            sv[i] = score[id];
            indeg[i] = 0;
        }
    }
}

__global__ void sort_local_kernel(unsigned long long* __restrict__ keys,
                                  const float* __restrict__ score,
                                  int* __restrict__ idx, float* __restrict__ sv,
                                  int* __restrict__ newid, int* __restrict__ indeg,
                                  int ksel, int do_ext) {
    __shared__ unsigned long long sk[CHUNK];
    int t = threadIdx.x;
    int g0 = blockIdx.x * CHUNK;
    sk[t] = keys[g0 + t];
    sk[t + 1024] = keys[g0 + t + 1024];
    __syncthreads();
    for (int k = 2; k <= CHUNK; k <<= 1) {
        for (int j = k >> 1; j > 0; j >>= 1) {
            int i = ((t / j) * 2 * j) + (t % j);
            int ixj = i + j;
            bool up = (((g0 + i) & k) == 0);
            unsigned long long a = sk[i], bb = sk[ixj];
            if ((a > bb) == up) { sk[i] = bb; sk[ixj] = a; }
            __syncthreads();
        }
    }
    keys[g0 + t] = sk[t];
    keys[g0 + t + 1024] = sk[t + 1024];
    if (do_ext) do_extract2(sk, g0, t, score, idx, sv, newid, indeg, ksel);
}

__global__ void sort_cross_kernel(unsigned long long* __restrict__ keys,
                                  int n, int k, int j) {
    int t = blockIdx.x * 256 + threadIdx.x;
    if (t >= n / 2) return;
    int i = ((t / j) * 2 * j) + (t % j);
    int ixj = i + j;
    bool up = ((i & k) == 0);
    unsigned long long a = keys[i], bb = keys[ixj];
    if ((a > bb) == up) { keys[i] = bb; keys[ixj] = a; }
}

__global__ void sort_finish_kernel(unsigned long long* __restrict__ keys, int k,
                                   const float* __restrict__ score,
                                   int* __restrict__ idx, float* __restrict__ sv,
                                   int* __restrict__ newid, int* __restrict__ indeg,
                                   int ksel, int do_ext) {
    __shared__ unsigned long long sk[CHUNK];
    int t = threadIdx.x;
    int g0 = blockIdx.x * CHUNK;
    sk[t] = keys[g0 + t];
    sk[t + 1024] = keys[g0 + t + 1024];
    __syncthreads();
    for (int j = 1024; j > 0; j >>= 1) {
        int i = ((t / j) * 2 * j) + (t % j);
        int ixj = i + j;
        bool up = (((g0 + i) & k) == 0);
        unsigned long long a = sk[i], bb = sk[ixj];
        if ((a > bb) == up) { sk[i] = bb; sk[ixj] = a; }
        __syncthreads();
    }
    keys[g0 + t] = sk[t];
    keys[g0 + t + 1024] = sk[t + 1024];
    if (do_ext) do_extract2(sk, g0, t, score, idx, sv, newid, indeg, ksel);
}

// ============================================================================
// Pool (32 new nodes/block): gather+gate h, gather xs/perm, remap edges,
// next indeg count, block-reduced readout atomics (set-invariant).
// ============================================================================
__global__ void pool_kernel(const float* __restrict__ h, const float* __restrict__ xs,
                            const int* __restrict__ perm, const int* __restrict__ edges,
                            const int* __restrict__ idx, const float* __restrict__ sv,
                            const int* __restrict__ newid,
                            float* __restrict__ h2, float* __restrict__ xs2,
                            int* __restrict__ perm2, int* __restrict__ edges2,
                            int* __restrict__ indeg, int stage) {
    __shared__ int sidx[32];
    __shared__ float sg[32];
    int c = threadIdx.x;
    int a0 = blockIdx.x * 32;
    if (c < 32) {
        sidx[c] = idx[a0 + c];
        sg[c] = tanhf(sv[a0 + c]);
    }
    __syncthreads();
    float lmax = -3.4e38f, lsum = 0.f;
    for (int rr = 0; rr < 32; rr++) {
        int a = a0 + rr;
        int o = sidx[rr];
        float v = h[(size_t)o * HDIM + c] * sg[rr];
        h2[(size_t)a * HDIM + c] = v;
        xs2[(size_t)a * HDIM + c] = xs[(size_t)o * HDIM + c];
        lmax = fmaxf(lmax, v);
        lsum += v;
        if (c < 5) {
            int e = edges[o * 5 + c];
            int ne = (e >= 0) ? newid[e] : -1;
            edges2[a * 5 + c] = ne;
            if (ne >= 0) atomicAdd(&indeg[ne], 1);
        }
        if (c == 5) perm2[a] = (perm != nullptr) ? perm[o] : o;
    }
    atomicMax(&g_rmax[stage][c], ordf(lmax));
    atomicAdd(&g_rsum[stage][c], lsum);
}

// ============================================================================
// Final MLP + log_softmax
// ============================================================================
__global__ void mlp_kernel(const float* __restrict__ L1w, const float* __restrict__ L1b,
                           const float* __restrict__ L2w, const float* __restrict__ L2b,
                           const float* __restrict__ L3w, const float* __restrict__ L3b,
                           float* __restrict__ out) {
    __shared__ float zin[256], z1[128], z2[64], z3[40];
    int t = threadIdx.x;
    if (t < 128) {
        zin[t] = deco(g_rmax[0][t]) + deco(g_rmax[1][t]) + deco(g_rmax[2][t]);
        zin[128 + t] = g_rsum[0][t] / 4096.f + g_rsum[1][t] / 2048.f + g_rsum[2][t] / 1024.f;
    }
    __syncthreads();
    if (t < 128) {
        float a = 0.f;
        for (int i = 0; i < 256; i++) a = fmaf(zin[i], L1w[i * 128 + t], a);
        z1[t] = fmaxf(a + L1b[t], 0.f);
    }
    __syncthreads();
    if (t < 64) {
        float a = 0.f;
        for (int i = 0; i < 128; i++) a = fmaf(z1[i], L2w[i * 64 + t], a);
        z2[t] = fmaxf(a + L2b[t], 0.f);
    }
    __syncthreads();
    if (t < 40) {
        float a = 0.f;
        for (int i = 0; i < 64; i++) a = fmaf(z2[i], L3w[i * 40 + t], a);
        z3[t] = a + L3b[t];
    }
    __syncthreads();
    if (t == 0) {
        float m = z3[0];
        for (int i = 1; i < 40; i++) m = fmaxf(m, z3[i]);
        float s = 0.f;
        for (int i = 0; i < 40; i++) s += expf(z3[i] - m);
        float l = m + logf(s);
        for (int i = 0; i < 40; i++) out[i] = z3[i] - l;
    }
}

__global__ void outxp_kernel(const float* __restrict__ xs, const int* __restrict__ perm,
                             float* __restrict__ out) {
    int i = blockIdx.x * 256 + threadIdx.x;
    if (i < 1024 * HDIM) out[40 + i] = xs[i];
    else if (i < 1024 * HDIM + 1024)
        out[40 + 1024 * HDIM + (i - 1024 * HDIM)] = (float)perm[i - 1024 * HDIM];
}

__global__ void a3_kernel(const int* __restrict__ edges, float* __restrict__ out) {
    int b = blockIdx.x;
    float* row = out + (size_t)b * 1024;
    for (int i = threadIdx.x; i < 1024; i += 256) row[i] = 0.f;
    __syncthreads();
    if (threadIdx.x == 0) {
        row[b] = 1.f;
        #pragma unroll
        for (int e = 0; e < 5; e++) {
            int tgt = edges[b * 5 + e];
            if (tgt >= 0) row[tgt] = 1.f;
        }
    }
}

// ============================================================================
// Host launcher
// ============================================================================
extern "C" void kernel_launch(void* const* d_in, const int* in_sizes, int n_in,
                              void* d_out, int out_size) {
    (void)in_sizes; (void)n_in; (void)out_size;
    const float* x0  = (const float*)d_in[0];
    const float* W[3]  = {(const float*)d_in[2], (const float*)d_in[4], (const float*)d_in[6]};
    const float* bb[3] = {(const float*)d_in[3], (const float*)d_in[5], (const float*)d_in[7]};
    const float* Wp[3] = {(const float*)d_in[8], (const float*)d_in[10], (const float*)d_in[12]};
    const float* bp[3] = {(const float*)d_in[9], (const float*)d_in[11], (const float*)d_in[13]};
    const float* L1w = (const float*)d_in[14];
    const float* L1b = (const float*)d_in[15];
    const float* L2w = (const float*)d_in[16];
    const float* L2b = (const float*)d_in[17];
    const float* L3w = (const float*)d_in[18];
    const float* L3b = (const float*)d_in[19];
    float* out = (float*)d_out;

    float *p_y, *p_hA, *p_hB, *p_dinv, *p_z, *p_score, *p_sv, *p_xsb, *p_part;
    int *p_edgesb, *p_indeg, *p_idx, *p_newid, *p_permb;
    unsigned char* p_mask;
    unsigned long long* p_keys;
    cudaGetSymbolAddress((void**)&p_edgesb, g_edges);
    cudaGetSymbolAddress((void**)&p_y, g_y);
    cudaGetSymbolAddress((void**)&p_hA, g_hA);
    cudaGetSymbolAddress((void**)&p_hB, g_hB);
    cudaGetSymbolAddress((void**)&p_xsb, g_xs);
    cudaGetSymbolAddress((void**)&p_permb, g_perm);
    cudaGetSymbolAddress((void**)&p_indeg, g_indeg);
    cudaGetSymbolAddress((void**)&p_dinv, g_dinv);
    cudaGetSymbolAddress((void**)&p_z, g_z);
    cudaGetSymbolAddress((void**)&p_score, g_score);
    cudaGetSymbolAddress((void**)&p_keys, g_keys);
    cudaGetSymbolAddress((void**)&p_idx, g_idx);
    cudaGetSymbolAddress((void**)&p_sv, g_sv);
    cudaGetSymbolAddress((void**)&p_newid, g_newid);
    cudaGetSymbolAddress((void**)&p_part, g_part);
    cudaGetSymbolAddress((void**)&p_mask, g_mask);

    int* p_edges[2] = {p_edgesb, p_edgesb + NMAX * 5};
    float* p_xs[2] = {p_xsb, p_xsb + (size_t)NMAX * HDIM};
    int* p_perm[2] = {p_permb, p_permb + NMAX};

    init_kernel<<<NMAX / 256, 256>>>(p_edges[0], p_indeg);

    for (int s = 0; s < 3; s++) {
        int n = NMAX >> s;
        int k = n >> 1;
        int* ecur = p_edges[s & 1];
        int* enext = p_edges[(s + 1) & 1];
        const float* hin = (s == 0) ? x0 : p_hB;
        const float* xin = (s == 0) ? x0 : p_xs[(s - 1) & 1];
        const int* pin = (s == 0) ? nullptr : p_perm[(s - 1) & 1];

        dinvhubs_kernel<<<1, 1024>>>(p_indeg, p_dinv, n);

        // feature + score pipeline (score bits == R4)
        gemmF_kernel<<<n / RPB, 128>>>(hin, W[s], bb[s], p_dinv, ecur,
                                       p_y, p_hA, p_mask);
        hubpartF_kernel<<<CHUNKS, 128>>>(p_y, p_dinv, p_mask, p_part, n);
        zdotSK_kernel<<<(n + 7) / 8, 256>>>(p_hA, Wp[s], p_dinv, bp[s],
                                            p_z, p_score, p_keys, n);
        hubfix2_kernel<<<1, 256>>>(p_part, p_dinv, bb[s], Wp[s], bp[s], p_mask,
                                   p_hA, p_z, p_score, p_keys, n);

        // multiblock bitonic sort (+ fused extract on final pass)
        int nblk = n / CHUNK;
        sort_local_kernel<<<nblk, 1024>>>(p_keys, p_score, p_idx, p_sv,
                                          p_newid, p_indeg, k, (n == CHUNK) ? 1 : 0);
        for (int kk = 2 * CHUNK; kk <= n; kk <<= 1) {
            for (int j = kk >> 1; j >= CHUNK; j >>= 1)
                sort_cross_kernel<<<(n / 2 + 255) / 256, 256>>>(p_keys, n, kk, j);
            sort_finish_kernel<<<nblk, 1024>>>(p_keys, kk, p_score, p_idx, p_sv,
                                               p_newid, p_indeg, k,
                                               (kk == n) ? 1 : 0);
        }

        pool_kernel<<<k / 32, 128>>>(p_hA, xin, pin, ecur, p_idx, p_sv, p_newid,
                                     p_hB, p_xs[s & 1], p_perm[s & 1], enext,
                                     p_indeg, s);
    }

    mlp_kernel<<<1, 256>>>(L1w, L1b, L2w, L2b, L3w, L3b, out);
    outxp_kernel<<<(1024 * HDIM + 1024 + 255) / 256, 256>>>(p_xs[0], p_perm[0], out);
    a3_kernel<<<1024, 256>>>(p_edges[1], out + 40 + 1024 * HDIM + 1024);
}

// round 9
// speedup vs baseline: 1.1676x; 1.1676x over previous
#include <cuda_runtime.h>
#include <cstdint>

#define NMAX 8192
#define HDIM 128
#define RPB 32      // rows per gemm block
#define CHUNK 2048  // sort chunk per block
#define CHUNKS 64   // hub-partial chunks (R4-exact)

// ============================================================================
// Device scratch
// ============================================================================
__device__ int   g_edges[2][NMAX * 5];
__device__ float g_y[NMAX * HDIM];
__device__ float g_hA[NMAX * HDIM];
__device__ float g_hB[NMAX * HDIM];
__device__ float g_xs[2][NMAX * HDIM];
__device__ int   g_perm[2][NMAX];
__device__ int   g_indeg[NMAX];
__device__ float g_dinv[NMAX];
__device__ float g_z[NMAX];
__device__ float g_score[NMAX];
__device__ unsigned long long g_keys[NMAX];
__device__ int   g_idx[NMAX];
__device__ float g_sv[NMAX];
__device__ int   g_newid[NMAX];
__device__ int   g_hubs[5];
__device__ int   g_nhubs;
__device__ float g_part[CHUNKS * 5 * HDIM];
__device__ __align__(8) unsigned char g_mask[NMAX];
__device__ unsigned g_rmax[3][HDIM];
__device__ float g_rsum[3][HDIM];

// ============================================================================
// Helpers
// ============================================================================
__device__ __forceinline__ unsigned ordf(float v) {
    unsigned u = __float_as_uint(v);
    return (u & 0x80000000u) ? ~u : (u | 0x80000000u);
}
__device__ __forceinline__ float deco(unsigned e) {
    unsigned u = (e & 0x80000000u) ? (e & 0x7fffffffu) : ~e;
    return __uint_as_float(u);
}

// ============================================================================
// Init: degenerate stage-0 edges (eye*inf NaN semantics), closed-form indeg,
// zero readout accumulators.
// ============================================================================
__global__ void init_kernel(int* __restrict__ eout, int* __restrict__ indeg) {
    int i = blockIdx.x * 256 + threadIdx.x;
    if (i < NMAX) {
        int pos = 0;
        #pragma unroll
        for (int j = 0; j < 5; j++)
            if (j != i && pos < 4) eout[i * 5 + (pos++)] = j;
        eout[i * 5 + 4] = -1;
        indeg[i] = (i < 4) ? (NMAX - 1) : ((i == 4) ? 4 : 0);
    }
    if (i < 3 * HDIM) {
        (&g_rmax[0][0])[i] = 0u;
        (&g_rsum[0][0])[i] = 0.f;
    }
}

// ============================================================================
// dinv + hub detection (1 block) — dinv expression identical to R4
// ============================================================================
__global__ void dinvhubs_kernel(const int* __restrict__ indeg,
                                float* __restrict__ dinv, int n) {
    __shared__ int cnt;
    __shared__ int sl[16];
    int t = threadIdx.x;
    if (t == 0) cnt = 0;
    __syncthreads();
    for (int i = t; i < n; i += 1024) {
        int d = indeg[i];
        float deg = 1.f + (float)d;
        dinv[i] = 1.0f / sqrtf(deg);
        if (d > 0) {
            int p = atomicAdd(&cnt, 1);
            if (p < 16) sl[p] = i;
        }
    }
    __syncthreads();
    if (t == 0) {
        int m = cnt < 5 ? cnt : 5;
        for (int i = 1; i < m; i++) {
            int v = sl[i], j = i - 1;
            while (j >= 0 && sl[j] > v) { sl[j + 1] = sl[j]; j--; }
            sl[j + 1] = v;
        }
        g_nhubs = m;
        #pragma unroll
        for (int k = 0; k < 5; k++) g_hubs[k] = (k < m) ? sl[k] : -1;
    }
}

// ============================================================================
// Per-row hub mask (R6-verbatim boolean)
// ============================================================================
__global__ void mask_kernel(const int* __restrict__ edges,
                            unsigned char* __restrict__ mask, int n) {
    __shared__ int shub[5];
    if (threadIdx.x < 5) shub[threadIdx.x] = g_hubs[threadIdx.x];
    __syncthreads();
    int r = blockIdx.x * 256 + threadIdx.x;
    if (r >= n) return;
    int e0 = edges[r * 5 + 0], e1 = edges[r * 5 + 1], e2 = edges[r * 5 + 2];
    int e3 = edges[r * 5 + 3], e4 = edges[r * 5 + 4];
    unsigned m = 0;
    #pragma unroll
    for (int k = 0; k < 5; k++) {
        int hv = shub[k];
        bool hit = (hv >= 0) &&
                   (e0 == hv || e1 == hv || e2 == hv || e3 == hv || e4 == hv || r == hv);
        if (hit) m |= 1u << k;
    }
    mask[r] = (unsigned char)m;
}

// ============================================================================
// Fused GEMM + base hA: 256 threads, 32 rows/block, 16 rows/thread.
// Each (row,col) ascending-k fmaf chain is bit-identical to R4.
// ============================================================================
__global__ void gemmF_kernel(const float* __restrict__ h, const float* __restrict__ W,
                             const float* __restrict__ b, const float* __restrict__ dinv,
                             float* __restrict__ y, float* __restrict__ hA) {
    __shared__ float hs[RPB][HDIM];
    __shared__ float sdi[RPB];
    const int t = threadIdx.x;
    const int c = t & 127;
    const int rb = (t >> 7) * 16;       // 0 or 16
    const int r0 = blockIdx.x * RPB;
    if (t < RPB) sdi[t] = dinv[r0 + t];
    #pragma unroll
    for (int l = 0; l < 16; l++) {
        int id = l * 256 + t;
        int rr = id >> 7, cc = id & 127;
        hs[rr][cc] = h[(size_t)(r0 + rr) * HDIM + cc];
    }
    __syncthreads();

    float acc[16];
    #pragma unroll
    for (int r = 0; r < 16; r++) acc[r] = 0.f;
    #pragma unroll 4
    for (int k = 0; k < HDIM; k++) {
        float w = W[k * HDIM + c];
        #pragma unroll
        for (int r = 0; r < 16; r++) acc[r] = fmaf(hs[rb + r][k], w, acc[r]);
    }
    float bc = b[c];
    #pragma unroll
    for (int r = 0; r < 16; r++) {
        int rr = rb + r;
        y[(size_t)(r0 + rr) * HDIM + c] = acc[r];
        float dc = sdi[rr];
        float v = fmaf(dc * dc, acc[r], bc);
        hA[(size_t)(r0 + rr) * HDIM + c] = fmaxf(v, 0.f);
    }
}

// ============================================================================
// Hub partials: 64 chunks, ascending rows, fadd chain (R4 bits).
// 8-wide batches with explicit double buffering; u64 mask load.
// ============================================================================
__global__ void hubpartF_kernel(const float* __restrict__ y, const float* __restrict__ dinv,
                                const unsigned char* __restrict__ mask,
                                float* __restrict__ part, int n) {
    int f = threadIdx.x;
    int ch = blockIdx.x;
    int rpc = n >> 6;   // 128/64/32, divisible by 8
    int rbeg = ch * rpc;
    float acc[5] = {0.f, 0.f, 0.f, 0.f, 0.f};

    float wv[2][8];
    unsigned long long mm[2];

    // prefetch batch 0
    mm[0] = *(const unsigned long long*)(mask + rbeg);
    #pragma unroll
    for (int q = 0; q < 8; q++)
        wv[0][q] = dinv[rbeg + q] * y[(size_t)(rbeg + q) * HDIM + f];

    int nb = rpc >> 3;
    for (int bidx = 0; bidx < nb; bidx++) {
        int cur = bidx & 1;
        if (bidx + 1 < nb) {
            int rb = rbeg + (bidx + 1) * 8;
            mm[cur ^ 1] = *(const unsigned long long*)(mask + rb);
            #pragma unroll
            for (int q = 0; q < 8; q++)
                wv[cur ^ 1][q] = dinv[rb + q] * y[(size_t)(rb + q) * HDIM + f];
        }
        unsigned long long m = mm[cur];
        #pragma unroll
        for (int q = 0; q < 8; q++) {
            unsigned mb = (unsigned)(m >> (8 * q)) & 0xffu;
            #pragma unroll
            for (int k = 0; k < 5; k++)
                if ((mb >> k) & 1u) acc[k] += wv[cur][q];
        }
    }
    #pragma unroll
    for (int k = 0; k < 5; k++) part[(ch * 5 + k) * HDIM + f] = acc[k];
}

// R4-verbatim: reduce chunks ascending, write hub hA rows
__global__ void hubfixF_kernel(const float* __restrict__ part, const float* __restrict__ dinv,
                               const float* __restrict__ b, float* __restrict__ out) {
    int k = blockIdx.x;
    if (k >= g_nhubs) return;
    int f = threadIdx.x;
    float S = 0.f;
    for (int ch = 0; ch < CHUNKS; ch++) S += part[(ch * 5 + k) * HDIM + f];
    int c = g_hubs[k];
    float v = fmaf(dinv[c], S, b[f]);
    out[(size_t)c * HDIM + f] = fmaxf(v, 0.f);
}

// ============================================================================
// z + base score + key (fused; bits == R4)
// ============================================================================
__global__ void zdotSK_kernel(const float* __restrict__ h, const float* __restrict__ Wp,
                              const float* __restrict__ dinv, const float* __restrict__ bp,
                              float* __restrict__ z, float* __restrict__ score,
                              unsigned long long* __restrict__ keys, int n) {
    int w = threadIdx.x >> 5, lane = threadIdx.x & 31;
    int r = blockIdx.x * 8 + w;
    if (r >= n) return;
    float s = 0.f;
    #pragma unroll
    for (int kk = lane; kk < HDIM; kk += 32)
        s = fmaf(h[(size_t)r * HDIM + kk], Wp[kk], s);
    #pragma unroll
    for (int o = 16; o > 0; o >>= 1) s += __shfl_down_sync(0xffffffffu, s, o);
    if (lane == 0) {
        z[r] = s;
        float dc = dinv[r];
        float sc = fmaf(dc * dc, s, bp[0]);
        score[r] = sc;
        keys[r] = ((unsigned long long)(~ordf(sc)) << 32) | (unsigned)r;
    }
}

// R4-verbatim hub score (5 blocks, 256 threads, strided, tree) + key pack
__global__ void hubfixSK_kernel(const float* __restrict__ z, const float* __restrict__ dinv,
                                const unsigned char* __restrict__ mask,
                                const float* __restrict__ bp,
                                float* __restrict__ score,
                                unsigned long long* __restrict__ keys, int n) {
    int k = blockIdx.x;
    if (k >= g_nhubs) return;
    int hub = g_hubs[k];
    __shared__ float red[256];
    int t = threadIdx.x;
    float p = 0.f;
    for (int r = t; r < n; r += 256) {
        if ((mask[r] >> k) & 1u) p += dinv[r] * z[r];
    }
    red[t] = p;
    __syncthreads();
    for (int o = 128; o > 0; o >>= 1) {
        if (t < o) red[t] += red[t + o];
        __syncthreads();
    }
    if (t == 0) {
        float sc = fmaf(dinv[hub], red[0], bp[0]);
        score[hub] = sc;
        keys[hub] = ((unsigned long long)(~ordf(sc)) << 32) | (unsigned)hub;
    }
}

// ============================================================================
// Multi-block bitonic sort (+ fused extract on the final pass)
// ============================================================================
__device__ __forceinline__ void do_extract2(const unsigned long long* sk, int g0, int t,
                                            const float* __restrict__ score,
                                            int* __restrict__ idx, float* __restrict__ sv,
                                            int* __restrict__ newid, int* __restrict__ indeg,
                                            int ksel) {
    #pragma unroll
    for (int h = 0; h < 2; h++) {
        int li = t + h * 1024;
        int i = g0 + li;
        int id = (int)(sk[li] & 0xffffffffull);
        newid[id] = (i < ksel) ? i : -1;
        if (i < ksel) {
            idx[i] = id;
            sv[i] = score[id];
            indeg[i] = 0;
        }
    }
}

__global__ void sort_local_kernel(unsigned long long* __restrict__ keys,
                                  const float* __restrict__ score,
                                  int* __restrict__ idx, float* __restrict__ sv,
                                  int* __restrict__ newid, int* __restrict__ indeg,
                                  int ksel, int do_ext) {
    __shared__ unsigned long long sk[CHUNK];
    int t = threadIdx.x;
    int g0 = blockIdx.x * CHUNK;
    sk[t] = keys[g0 + t];
    sk[t + 1024] = keys[g0 + t + 1024];
    __syncthreads();
    for (int k = 2; k <= CHUNK; k <<= 1) {
        for (int j = k >> 1; j > 0; j >>= 1) {
            int i = ((t / j) * 2 * j) + (t % j);
            int ixj = i + j;
            bool up = (((g0 + i) & k) == 0);
            unsigned long long a = sk[i], bb = sk[ixj];
            if ((a > bb) == up) { sk[i] = bb; sk[ixj] = a; }
            __syncthreads();
        }
    }
    keys[g0 + t] = sk[t];
    keys[g0 + t + 1024] = sk[t + 1024];
    if (do_ext) do_extract2(sk, g0, t, score, idx, sv, newid, indeg, ksel);
}

__global__ void sort_cross_kernel(unsigned long long* __restrict__ keys,
                                  int n, int k, int j) {
    int t = blockIdx.x * 256 + threadIdx.x;
    if (t >= n / 2) return;
    int i = ((t / j) * 2 * j) + (t % j);
    int ixj = i + j;
    bool up = ((i & k) == 0);
    unsigned long long a = keys[i], bb = keys[ixj];
    if ((a > bb) == up) { keys[i] = bb; keys[ixj] = a; }
}

__global__ void sort_finish_kernel(unsigned long long* __restrict__ keys, int k,
                                   const float* __restrict__ score,
                                   int* __restrict__ idx, float* __restrict__ sv,
                                   int* __restrict__ newid, int* __restrict__ indeg,
                                   int ksel, int do_ext) {
    __shared__ unsigned long long sk[CHUNK];
    int t = threadIdx.x;
    int g0 = blockIdx.x * CHUNK;
    sk[t] = keys[g0 + t];
    sk[t + 1024] = keys[g0 + t + 1024];
    __syncthreads();
    for (int j = 1024; j > 0; j >>= 1) {
        int i = ((t / j) * 2 * j) + (t % j);
        int ixj = i + j;
        bool up = (((g0 + i) & k) == 0);
        unsigned long long a = sk[i], bb = sk[ixj];
        if ((a > bb) == up) { sk[i] = bb; sk[ixj] = a; }
        __syncthreads();
    }
    keys[g0 + t] = sk[t];
    keys[g0 + t + 1024] = sk[t + 1024];
    if (do_ext) do_extract2(sk, g0, t, score, idx, sv, newid, indeg, ksel);
}

// ============================================================================
// Pool (32 new nodes/block): gather+gate h, gather xs/perm, remap edges,
// next indeg count, block-reduced readout atomics (set-invariant).
// ============================================================================
__global__ void pool_kernel(const float* __restrict__ h, const float* __restrict__ xs,
                            const int* __restrict__ perm, const int* __restrict__ edges,
                            const int* __restrict__ idx, const float* __restrict__ sv,
                            const int* __restrict__ newid,
                            float* __restrict__ h2, float* __restrict__ xs2,
                            int* __restrict__ perm2, int* __restrict__ edges2,
                            int* __restrict__ indeg, int stage) {
    __shared__ int sidx[32];
    __shared__ float sg[32];
    int c = threadIdx.x;
    int a0 = blockIdx.x * 32;
    if (c < 32) {
        sidx[c] = idx[a0 + c];
        sg[c] = tanhf(sv[a0 + c]);
    }
    __syncthreads();
    float lmax = -3.4e38f, lsum = 0.f;
    for (int rr = 0; rr < 32; rr++) {
        int a = a0 + rr;
        int o = sidx[rr];
        float v = h[(size_t)o * HDIM + c] * sg[rr];
        h2[(size_t)a * HDIM + c] = v;
        xs2[(size_t)a * HDIM + c] = xs[(size_t)o * HDIM + c];
        lmax = fmaxf(lmax, v);
        lsum += v;
        if (c < 5) {
            int e = edges[o * 5 + c];
            int ne = (e >= 0) ? newid[e] : -1;
            edges2[a * 5 + c] = ne;
            if (ne >= 0) atomicAdd(&indeg[ne], 1);
        }
        if (c == 5) perm2[a] = (perm != nullptr) ? perm[o] : o;
    }
    atomicMax(&g_rmax[stage][c], ordf(lmax));
    atomicAdd(&g_rsum[stage][c], lsum);
}

// ============================================================================
// Final MLP + log_softmax
// ============================================================================
__global__ void mlp_kernel(const float* __restrict__ L1w, const float* __restrict__ L1b,
                           const float* __restrict__ L2w, const float* __restrict__ L2b,
                           const float* __restrict__ L3w, const float* __restrict__ L3b,
                           float* __restrict__ out) {
    __shared__ float zin[256], z1[128], z2[64], z3[40];
    int t = threadIdx.x;
    if (t < 128) {
        zin[t] = deco(g_rmax[0][t]) + deco(g_rmax[1][t]) + deco(g_rmax[2][t]);
        zin[128 + t] = g_rsum[0][t] / 4096.f + g_rsum[1][t] / 2048.f + g_rsum[2][t] / 1024.f;
    }
    __syncthreads();
    if (t < 128) {
        float a = 0.f;
        for (int i = 0; i < 256; i++) a = fmaf(zin[i], L1w[i * 128 + t], a);
        z1[t] = fmaxf(a + L1b[t], 0.f);
    }
    __syncthreads();
    if (t < 64) {
        float a = 0.f;
        for (int i = 0; i < 128; i++) a = fmaf(z1[i], L2w[i * 64 + t], a);
        z2[t] = fmaxf(a + L2b[t], 0.f);
    }
    __syncthreads();
    if (t < 40) {
        float a = 0.f;
        for (int i = 0; i < 64; i++) a = fmaf(z2[i], L3w[i * 40 + t], a);
        z3[t] = a + L3b[t];
    }
    __syncthreads();
    if (t == 0) {
        float m = z3[0];
        for (int i = 1; i < 40; i++) m = fmaxf(m, z3[i]);
        float s = 0.f;
        for (int i = 0; i < 40; i++) s += expf(z3[i] - m);
        float l = m + logf(s);
        for (int i = 0; i < 40; i++) out[i] = z3[i] - l;
    }
}

__global__ void outxp_kernel(const float* __restrict__ xs, const int* __restrict__ perm,
                             float* __restrict__ out) {
    int i = blockIdx.x * 256 + threadIdx.x;
    if (i < 1024 * HDIM) out[40 + i] = xs[i];
    else if (i < 1024 * HDIM + 1024)
        out[40 + 1024 * HDIM + (i - 1024 * HDIM)] = (float)perm[i - 1024 * HDIM];
}

__global__ void a3_kernel(const int* __restrict__ edges, float* __restrict__ out) {
    int b = blockIdx.x;
    float* row = out + (size_t)b * 1024;
    for (int i = threadIdx.x; i < 1024; i += 256) row[i] = 0.f;
    __syncthreads();
    if (threadIdx.x == 0) {
        row[b] = 1.f;
        #pragma unroll
        for (int e = 0; e < 5; e++) {
            int tgt = edges[b * 5 + e];
            if (tgt >= 0) row[tgt] = 1.f;
        }
    }
}

// ============================================================================
// Host launcher
// ============================================================================
extern "C" void kernel_launch(void* const* d_in, const int* in_sizes, int n_in,
                              void* d_out, int out_size) {
    (void)in_sizes; (void)n_in; (void)out_size;
    const float* x0  = (const float*)d_in[0];
    const float* W[3]  = {(const float*)d_in[2], (const float*)d_in[4], (const float*)d_in[6]};
    const float* bb[3] = {(const float*)d_in[3], (const float*)d_in[5], (const float*)d_in[7]};
    const float* Wp[3] = {(const float*)d_in[8], (const float*)d_in[10], (const float*)d_in[12]};
    const float* bp[3] = {(const float*)d_in[9], (const float*)d_in[11], (const float*)d_in[13]};
    const float* L1w = (const float*)d_in[14];
    const float* L1b = (const float*)d_in[15];
    const float* L2w = (const float*)d_in[16];
    const float* L2b = (const float*)d_in[17];
    const float* L3w = (const float*)d_in[18];
    const float* L3b = (const float*)d_in[19];
    float* out = (float*)d_out;

    float *p_y, *p_hA, *p_hB, *p_dinv, *p_z, *p_score, *p_sv, *p_xsb, *p_part;
    int *p_edgesb, *p_indeg, *p_idx, *p_newid, *p_permb;
    unsigned char* p_mask;
    unsigned long long* p_keys;
    cudaGetSymbolAddress((void**)&p_edgesb, g_edges);
    cudaGetSymbolAddress((void**)&p_y, g_y);
    cudaGetSymbolAddress((void**)&p_hA, g_hA);
    cudaGetSymbolAddress((void**)&p_hB, g_hB);
    cudaGetSymbolAddress((void**)&p_xsb, g_xs);
    cudaGetSymbolAddress((void**)&p_permb, g_perm);
    cudaGetSymbolAddress((void**)&p_indeg, g_indeg);
    cudaGetSymbolAddress((void**)&p_dinv, g_dinv);
    cudaGetSymbolAddress((void**)&p_z, g_z);
    cudaGetSymbolAddress((void**)&p_score, g_score);
    cudaGetSymbolAddress((void**)&p_keys, g_keys);
    cudaGetSymbolAddress((void**)&p_idx, g_idx);
    cudaGetSymbolAddress((void**)&p_sv, g_sv);
    cudaGetSymbolAddress((void**)&p_newid, g_newid);
    cudaGetSymbolAddress((void**)&p_part, g_part);
    cudaGetSymbolAddress((void**)&p_mask, g_mask);

    int* p_edges[2] = {p_edgesb, p_edgesb + NMAX * 5};
    float* p_xs[2] = {p_xsb, p_xsb + (size_t)NMAX * HDIM};
    int* p_perm[2] = {p_permb, p_permb + NMAX};

    init_kernel<<<NMAX / 256, 256>>>(p_edges[0], p_indeg);

    for (int s = 0; s < 3; s++) {
        int n = NMAX >> s;
        int k = n >> 1;
        int nb = (n + 255) / 256;
        int* ecur = p_edges[s & 1];
        int* enext = p_edges[(s + 1) & 1];
        const float* hin = (s == 0) ? x0 : p_hB;
        const float* xin = (s == 0) ? x0 : p_xs[(s - 1) & 1];
        const int* pin = (s == 0) ? nullptr : p_perm[(s - 1) & 1];

        dinvhubs_kernel<<<1, 1024>>>(p_indeg, p_dinv, n);
        mask_kernel<<<nb, 256>>>(ecur, p_mask, n);

        // feature + score pipeline (score bits == R4)
        gemmF_kernel<<<n / RPB, 256>>>(hin, W[s], bb[s], p_dinv, p_y, p_hA);
        hubpartF_kernel<<<CHUNKS, 128>>>(p_y, p_dinv, p_mask, p_part, n);
        hubfixF_kernel<<<5, 128>>>(p_part, p_dinv, bb[s], p_hA);
        zdotSK_kernel<<<(n + 7) / 8, 256>>>(p_hA, Wp[s], p_dinv, bp[s],
                                            p_z, p_score, p_keys, n);
        hubfixSK_kernel<<<5, 256>>>(p_z, p_dinv, p_mask, bp[s], p_score, p_keys, n);

        // multiblock bitonic sort (+ fused extract on final pass)
        int nblk = n / CHUNK;
        sort_local_kernel<<<nblk, 1024>>>(p_keys, p_score, p_idx, p_sv,
                                          p_newid, p_indeg, k, (n == CHUNK) ? 1 : 0);
        for (int kk = 2 * CHUNK; kk <= n; kk <<= 1) {
            for (int j = kk >> 1; j >= CHUNK; j >>= 1)
                sort_cross_kernel<<<(n / 2 + 255) / 256, 256>>>(p_keys, n, kk, j);
            sort_finish_kernel<<<nblk, 1024>>>(p_keys, kk, p_score, p_idx, p_sv,
                                               p_newid, p_indeg, k,
                                               (kk == n) ? 1 : 0);
        }

        pool_kernel<<<k / 32, 128>>>(p_hA, xin, pin, ecur, p_idx, p_sv, p_newid,
                                     p_hB, p_xs[s & 1], p_perm[s & 1], enext,
                                     p_indeg, s);
    }

    mlp_kernel<<<1, 256>>>(L1w, L1b, L2w, L2b, L3w, L3b, out);
    outxp_kernel<<<(1024 * HDIM + 1024 + 255) / 256, 256>>>(p_xs[0], p_perm[0], out);
    a3_kernel<<<1024, 256>>>(p_edges[1], out + 40 + 1024 * HDIM + 1024);
}

// round 10
// speedup vs baseline: 1.1871x; 1.0167x over previous
#include <cuda_runtime.h>
#include <cstdint>

#define NMAX 8192
#define HDIM 128
#define RPB 32      // rows per gemm block
#define CHUNK 2048  // sort chunk per block
#define CHUNKS 64   // hub-partial chunks (R4-exact)

// ============================================================================
// Device scratch
// ============================================================================
__device__ int   g_edges[2][NMAX * 5];
__device__ float g_y[NMAX * HDIM];
__device__ float g_hA[NMAX * HDIM];
__device__ float g_hB[NMAX * HDIM];
__device__ float g_xs[2][NMAX * HDIM];
__device__ int   g_perm[2][NMAX];
__device__ int   g_indeg[NMAX];
__device__ float g_dinv[NMAX];
__device__ float g_z[NMAX];
__device__ float g_score[NMAX];
__device__ unsigned long long g_keys[NMAX];
__device__ int   g_idx[NMAX];
__device__ float g_sv[NMAX];
__device__ int   g_newid[NMAX];
__device__ int   g_hubs[5];
__device__ int   g_nhubs;
__device__ float g_part[CHUNKS * 5 * HDIM];
__device__ __align__(8) unsigned char g_mask[NMAX];
__device__ unsigned g_rmax[3][HDIM];
__device__ float g_rsum[3][HDIM];

// ============================================================================
// Helpers
// ============================================================================
__device__ __forceinline__ unsigned ordf(float v) {
    unsigned u = __float_as_uint(v);
    return (u & 0x80000000u) ? ~u : (u | 0x80000000u);
}
__device__ __forceinline__ float deco(unsigned e) {
    unsigned u = (e & 0x80000000u) ? (e & 0x7fffffffu) : ~e;
    return __uint_as_float(u);
}
__device__ __forceinline__ unsigned long long pk2(float x, float y) {
    unsigned long long r;
    asm("mov.b64 %0, {%1, %2};" : "=l"(r)
        : "r"(__float_as_uint(x)), "r"(__float_as_uint(y)));
    return r;
}
__device__ __forceinline__ void up2(unsigned long long v, float& x, float& y) {
    unsigned a, b;
    asm("mov.b64 {%0, %1}, %2;" : "=r"(a), "=r"(b) : "l"(v));
    x = __uint_as_float(a);
    y = __uint_as_float(b);
}
__device__ __forceinline__ void fma2(unsigned long long& c,
                                     unsigned long long a,
                                     unsigned long long b) {
    asm("fma.rn.f32x2 %0, %1, %2, %3;" : "=l"(c) : "l"(a), "l"(b), "l"(c));
}

// ============================================================================
// Init: degenerate stage-0 edges (eye*inf NaN semantics), closed-form indeg,
// zero readout accumulators.
// ============================================================================
__global__ void init_kernel(int* __restrict__ eout, int* __restrict__ indeg) {
    int i = blockIdx.x * 256 + threadIdx.x;
    if (i < NMAX) {
        int pos = 0;
        #pragma unroll
        for (int j = 0; j < 5; j++)
            if (j != i && pos < 4) eout[i * 5 + (pos++)] = j;
        eout[i * 5 + 4] = -1;
        indeg[i] = (i < 4) ? (NMAX - 1) : ((i == 4) ? 4 : 0);
    }
    if (i < 3 * HDIM) {
        (&g_rmax[0][0])[i] = 0u;
        (&g_rsum[0][0])[i] = 0.f;
    }
}

// ============================================================================
// dinv + hub detection + per-row mask (merged; dinv/mask bits == R4/R6)
// ============================================================================
__global__ void dinvhubsmask_kernel(const int* __restrict__ indeg,
                                    const int* __restrict__ edges,
                                    float* __restrict__ dinv,
                                    unsigned char* __restrict__ mask, int n) {
    __shared__ int cnt;
    __shared__ int sl[16];
    __shared__ int shub[5];
    int t = threadIdx.x;
    if (t == 0) cnt = 0;
    __syncthreads();
    for (int i = t; i < n; i += 1024) {
        int d = indeg[i];
        float deg = 1.f + (float)d;
        dinv[i] = 1.0f / sqrtf(deg);
        if (d > 0) {
            int p = atomicAdd(&cnt, 1);
            if (p < 16) sl[p] = i;
        }
    }
    __syncthreads();
    if (t == 0) {
        int m = cnt < 5 ? cnt : 5;
        for (int i = 1; i < m; i++) {
            int v = sl[i], j = i - 1;
            while (j >= 0 && sl[j] > v) { sl[j + 1] = sl[j]; j--; }
            sl[j + 1] = v;
        }
        g_nhubs = m;
        #pragma unroll
        for (int k = 0; k < 5; k++) {
            int v = (k < m) ? sl[k] : -1;
            g_hubs[k] = v;
            shub[k] = v;
        }
    }
    __syncthreads();
    for (int r = t; r < n; r += 1024) {
        int e0 = edges[r * 5 + 0], e1 = edges[r * 5 + 1], e2 = edges[r * 5 + 2];
        int e3 = edges[r * 5 + 3], e4 = edges[r * 5 + 4];
        unsigned m = 0;
        #pragma unroll
        for (int k = 0; k < 5; k++) {
            int hv = shub[k];
            bool hit = (hv >= 0) &&
                       (e0 == hv || e1 == hv || e2 == hv || e3 == hv || e4 == hv || r == hv);
            if (hit) m |= 1u << k;
        }
        mask[r] = (unsigned char)m;
    }
}

// ============================================================================
// Mega GEMM: y = h@W via packed fma.rn.f32x2 (each lane == scalar ascending-k
// fmaf chain -> bit == R4). hA = relu(dinv^2*y+b) (bit == R4). Epilogue
// replays zdot's exact pattern (strided fmaf + shfl tree) on the smem hA tile
// -> z/score/keys bit == R4 for non-hub rows (hub rows overwritten later).
// 256 threads, 32 rows/block.
// ============================================================================
__global__ void gemmF_kernel(const float* __restrict__ h, const float* __restrict__ W,
                             const float* __restrict__ b, const float* __restrict__ Wp,
                             const float* __restrict__ bp, const float* __restrict__ dinv,
                             float* __restrict__ y, float* __restrict__ hA,
                             float* __restrict__ z, float* __restrict__ score,
                             unsigned long long* __restrict__ keys) {
    __shared__ __align__(16) float sbuf[HDIM * 34];  // hs_t[k][r] (stride 34) -> hAs[r][c]
    __shared__ float sdi[RPB];
    __shared__ float sWp[HDIM];
    const int t = threadIdx.x;
    const int c = t & 127;
    const int rb = (t >> 7) * 16;       // 0 or 16
    const int r0 = blockIdx.x * RPB;
    if (t < RPB) sdi[t] = dinv[r0 + t];
    if (t < HDIM) sWp[t] = Wp[t];
    #pragma unroll
    for (int l = 0; l < 16; l++) {
        int id = l * 256 + t;
        int rr = id >> 7, cc = id & 127;
        sbuf[cc * 34 + rr] = h[(size_t)(r0 + rr) * HDIM + cc];
    }
    __syncthreads();

    unsigned long long acc2[8];
    #pragma unroll
    for (int p = 0; p < 8; p++) acc2[p] = 0ull;
    #pragma unroll
    for (int k0 = 0; k0 < HDIM; k0 += 8) {
        float wv[8];
        #pragma unroll
        for (int q = 0; q < 8; q++) wv[q] = W[(k0 + q) * HDIM + c];
        #pragma unroll
        for (int q = 0; q < 8; q++) {
            unsigned long long w2 = pk2(wv[q], wv[q]);
            const float2* hp = (const float2*)&sbuf[(k0 + q) * 34 + rb];
            #pragma unroll
            for (int p = 0; p < 8; p++) {
                float2 h2 = hp[p];
                fma2(acc2[p], pk2(h2.x, h2.y), w2);
            }
        }
    }
    __syncthreads();   // all reads of hs_t done before overwrite

    float bc = b[c];
    #pragma unroll
    for (int p = 0; p < 8; p++) {
        float a0, a1;
        up2(acc2[p], a0, a1);
        int rr0 = rb + 2 * p, rr1 = rr0 + 1;
        y[(size_t)(r0 + rr0) * HDIM + c] = a0;
        y[(size_t)(r0 + rr1) * HDIM + c] = a1;
        float d0 = sdi[rr0], d1 = sdi[rr1];
        float v0 = fmaxf(fmaf(d0 * d0, a0, bc), 0.f);
        float v1 = fmaxf(fmaf(d1 * d1, a1, bc), 0.f);
        hA[(size_t)(r0 + rr0) * HDIM + c] = v0;
        hA[(size_t)(r0 + rr1) * HDIM + c] = v1;
        sbuf[rr0 * HDIM + c] = v0;
        sbuf[rr1 * HDIM + c] = v1;
    }
    __syncthreads();

    // zdot-bit-exact epilogue: warp w handles rows w*4..w*4+3
    int w = t >> 5, lane = t & 31;
    float bp0 = bp[0];
    #pragma unroll
    for (int q = 0; q < 4; q++) {
        int rr = w * 4 + q;
        float s = 0.f;
        #pragma unroll
        for (int kk = 0; kk < 4; kk++)
            s = fmaf(sbuf[rr * HDIM + lane + 32 * kk], sWp[lane + 32 * kk], s);
        #pragma unroll
        for (int o = 16; o > 0; o >>= 1) s += __shfl_down_sync(0xffffffffu, s, o);
        if (lane == 0) {
            int r = r0 + rr;
            z[r] = s;
            float dc = sdi[rr];
            float sc = fmaf(dc * dc, s, bp0);
            score[r] = sc;
            keys[r] = ((unsigned long long)(~ordf(sc)) << 32) | (unsigned)r;
        }
    }
}

// ============================================================================
// Hub partials: 64 chunks, ascending rows, fadd chain (R4 bits).
// 8-wide batches with explicit double buffering; u64 mask load.
// ============================================================================
__global__ void hubpartF_kernel(const float* __restrict__ y, const float* __restrict__ dinv,
                                const unsigned char* __restrict__ mask,
                                float* __restrict__ part, int n) {
    int f = threadIdx.x;
    int ch = blockIdx.x;
    int rpc = n >> 6;   // 128/64/32, divisible by 8
    int rbeg = ch * rpc;
    float acc[5] = {0.f, 0.f, 0.f, 0.f, 0.f};

    float wv[2][8];
    unsigned long long mm[2];

    mm[0] = *(const unsigned long long*)(mask + rbeg);
    #pragma unroll
    for (int q = 0; q < 8; q++)
        wv[0][q] = dinv[rbeg + q] * y[(size_t)(rbeg + q) * HDIM + f];

    int nb = rpc >> 3;
    for (int bidx = 0; bidx < nb; bidx++) {
        int cur = bidx & 1;
        if (bidx + 1 < nb) {
            int rb = rbeg + (bidx + 1) * 8;
            mm[cur ^ 1] = *(const unsigned long long*)(mask + rb);
            #pragma unroll
            for (int q = 0; q < 8; q++)
                wv[cur ^ 1][q] = dinv[rb + q] * y[(size_t)(rb + q) * HDIM + f];
        }
        unsigned long long m = mm[cur];
        #pragma unroll
        for (int q = 0; q < 8; q++) {
            unsigned mb = (unsigned)(m >> (8 * q)) & 0xffu;
            #pragma unroll
            for (int k = 0; k < 5; k++)
                if ((mb >> k) & 1u) acc[k] += wv[cur][q];
        }
    }
    #pragma unroll
    for (int k = 0; k < 5; k++) part[(ch * 5 + k) * HDIM + f] = acc[k];
}

// ============================================================================
// Hub fixup: chunk reduce (R4 bits) -> hub hA row -> hub z via zdot-bit-exact
// warp reduce (proven in R8). 5 parallel blocks.
// ============================================================================
__global__ void hubfixF_kernel(const float* __restrict__ part, const float* __restrict__ dinv,
                               const float* __restrict__ b, const float* __restrict__ Wp,
                               float* __restrict__ hA, float* __restrict__ z) {
    int k = blockIdx.x;
    if (k >= g_nhubs) return;
    __shared__ float hv[HDIM];
    int f = threadIdx.x;
    float S = 0.f;
    for (int ch = 0; ch < CHUNKS; ch++) S += part[(ch * 5 + k) * HDIM + f];
    int c = g_hubs[k];
    float v = fmaf(dinv[c], S, b[f]);
    v = fmaxf(v, 0.f);
    hA[(size_t)c * HDIM + f] = v;
    hv[f] = v;
    __syncthreads();
    if (f < 32) {
        float s = 0.f;
        #pragma unroll
        for (int kk = 0; kk < 4; kk++)
            s = fmaf(hv[f + 32 * kk], Wp[f + 32 * kk], s);
        #pragma unroll
        for (int o = 16; o > 0; o >>= 1) s += __shfl_down_sync(0xffffffffu, s, o);
        if (f == 0) z[c] = s;
    }
}

// R4-verbatim hub score (5 blocks, 256 threads, strided, tree) + key pack
__global__ void hubfixSK_kernel(const float* __restrict__ z, const float* __restrict__ dinv,
                                const unsigned char* __restrict__ mask,
                                const float* __restrict__ bp,
                                float* __restrict__ score,
                                unsigned long long* __restrict__ keys, int n) {
    int k = blockIdx.x;
    if (k >= g_nhubs) return;
    int hub = g_hubs[k];
    __shared__ float red[256];
    int t = threadIdx.x;
    float p = 0.f;
    for (int r = t; r < n; r += 256) {
        if ((mask[r] >> k) & 1u) p += dinv[r] * z[r];
    }
    red[t] = p;
    __syncthreads();
    for (int o = 128; o > 0; o >>= 1) {
        if (t < o) red[t] += red[t + o];
        __syncthreads();
    }
    if (t == 0) {
        float sc = fmaf(dinv[hub], red[0], bp[0]);
        score[hub] = sc;
        keys[hub] = ((unsigned long long)(~ordf(sc)) << 32) | (unsigned)hub;
    }
}

// ============================================================================
// Multi-block bitonic sort (+ fused extract on the final pass)
// ============================================================================
__device__ __forceinline__ void do_extract2(const unsigned long long* sk, int g0, int t,
                                            const float* __restrict__ score,
                                            int* __restrict__ idx, float* __restrict__ sv,
                                            int* __restrict__ newid, int* __restrict__ indeg,
                                            int ksel) {
    #pragma unroll
    for (int h = 0; h < 2; h++) {
        int li = t + h * 1024;
        int i = g0 + li;
        int id = (int)(sk[li] & 0xffffffffull);
        newid[id] = (i < ksel) ? i : -1;
        if (i < ksel) {
            idx[i] = id;
            sv[i] = score[id];
            indeg[i] = 0;
        }
    }
}

__global__ void sort_local_kernel(unsigned long long* __restrict__ keys,
                                  const float* __restrict__ score,
                                  int* __restrict__ idx, float* __restrict__ sv,
                                  int* __restrict__ newid, int* __restrict__ indeg,
                                  int ksel, int do_ext) {
    __shared__ unsigned long long sk[CHUNK];
    int t = threadIdx.x;
    int g0 = blockIdx.x * CHUNK;
    sk[t] = keys[g0 + t];
    sk[t + 1024] = keys[g0 + t + 1024];
    __syncthreads();
    for (int k = 2; k <= CHUNK; k <<= 1) {
        for (int j = k >> 1; j > 0; j >>= 1) {
            int i = ((t / j) * 2 * j) + (t % j);
            int ixj = i + j;
            bool up = (((g0 + i) & k) == 0);
            unsigned long long a = sk[i], bb = sk[ixj];
            if ((a > bb) == up) { sk[i] = bb; sk[ixj] = a; }
            __syncthreads();
        }
    }
    keys[g0 + t] = sk[t];
    keys[g0 + t + 1024] = sk[t + 1024];
    if (do_ext) do_extract2(sk, g0, t, score, idx, sv, newid, indeg, ksel);
}

__global__ void sort_cross_kernel(unsigned long long* __restrict__ keys,
                                  int n, int k, int j) {
    int t = blockIdx.x * 256 + threadIdx.x;
    if (t >= n / 2) return;
    int i = ((t / j) * 2 * j) + (t % j);
    int ixj = i + j;
    bool up = ((i & k) == 0);
    unsigned long long a = keys[i], bb = keys[ixj];
    if ((a > bb) == up) { keys[i] = bb; keys[ixj] = a; }
}

__global__ void sort_finish_kernel(unsigned long long* __restrict__ keys, int k,
                                   const float* __restrict__ score,
                                   int* __restrict__ idx, float* __restrict__ sv,
                                   int* __restrict__ newid, int* __restrict__ indeg,
                                   int ksel, int do_ext) {
    __shared__ unsigned long long sk[CHUNK];
    int t = threadIdx.x;
    int g0 = blockIdx.x * CHUNK;
    sk[t] = keys[g0 + t];
    sk[t + 1024] = keys[g0 + t + 1024];
    __syncthreads();
    for (int j = 1024; j > 0; j >>= 1) {
        int i = ((t / j) * 2 * j) + (t % j);
        int ixj = i + j;
        bool up = (((g0 + i) & k) == 0);
        unsigned long long a = sk[i], bb = sk[ixj];
        if ((a > bb) == up) { sk[i] = bb; sk[ixj] = a; }
        __syncthreads();
    }
    keys[g0 + t] = sk[t];
    keys[g0 + t + 1024] = sk[t + 1024];
    if (do_ext) do_extract2(sk, g0, t, score, idx, sv, newid, indeg, ksel);
}

// ============================================================================
// Pool (32 new nodes/block): gather+gate h, gather xs/perm, remap edges,
// next indeg count, block-reduced readout atomics (set-invariant).
// ============================================================================
__global__ void pool_kernel(const float* __restrict__ h, const float* __restrict__ xs,
                            const int* __restrict__ perm, const int* __restrict__ edges,
                            const int* __restrict__ idx, const float* __restrict__ sv,
                            const int* __restrict__ newid,
                            float* __restrict__ h2, float* __restrict__ xs2,
                            int* __restrict__ perm2, int* __restrict__ edges2,
                            int* __restrict__ indeg, int stage) {
    __shared__ int sidx[32];
    __shared__ float sg[32];
    int c = threadIdx.x;
    int a0 = blockIdx.x * 32;
    if (c < 32) {
        sidx[c] = idx[a0 + c];
        sg[c] = tanhf(sv[a0 + c]);
    }
    __syncthreads();
    float lmax = -3.4e38f, lsum = 0.f;
    for (int rr = 0; rr < 32; rr++) {
        int a = a0 + rr;
        int o = sidx[rr];
        float v = h[(size_t)o * HDIM + c] * sg[rr];
        h2[(size_t)a * HDIM + c] = v;
        xs2[(size_t)a * HDIM + c] = xs[(size_t)o * HDIM + c];
        lmax = fmaxf(lmax, v);
        lsum += v;
        if (c < 5) {
            int e = edges[o * 5 + c];
            int ne = (e >= 0) ? newid[e] : -1;
            edges2[a * 5 + c] = ne;
            if (ne >= 0) atomicAdd(&indeg[ne], 1);
        }
        if (c == 5) perm2[a] = (perm != nullptr) ? perm[o] : o;
    }
    atomicMax(&g_rmax[stage][c], ordf(lmax));
    atomicAdd(&g_rsum[stage][c], lsum);
}

// ============================================================================
// Final MLP + log_softmax
// ============================================================================
__global__ void mlp_kernel(const float* __restrict__ L1w, const float* __restrict__ L1b,
                           const float* __restrict__ L2w, const float* __restrict__ L2b,
                           const float* __restrict__ L3w, const float* __restrict__ L3b,
                           float* __restrict__ out) {
    __shared__ float zin[256], z1[128], z2[64], z3[40];
    int t = threadIdx.x;
    if (t < 128) {
        zin[t] = deco(g_rmax[0][t]) + deco(g_rmax[1][t]) + deco(g_rmax[2][t]);
        zin[128 + t] = g_rsum[0][t] / 4096.f + g_rsum[1][t] / 2048.f + g_rsum[2][t] / 1024.f;
    }
    __syncthreads();
    if (t < 128) {
        float a = 0.f;
        for (int i = 0; i < 256; i++) a = fmaf(zin[i], L1w[i * 128 + t], a);
        z1[t] = fmaxf(a + L1b[t], 0.f);
    }
    __syncthreads();
    if (t < 64) {
        float a = 0.f;
        for (int i = 0; i < 128; i++) a = fmaf(z1[i], L2w[i * 64 + t], a);
        z2[t] = fmaxf(a + L2b[t], 0.f);
    }
    __syncthreads();
    if (t < 40) {
        float a = 0.f;
        for (int i = 0; i < 64; i++) a = fmaf(z2[i], L3w[i * 40 + t], a);
        z3[t] = a + L3b[t];
    }
    __syncthreads();
    if (t == 0) {
        float m = z3[0];
        for (int i = 1; i < 40; i++) m = fmaxf(m, z3[i]);
        float s = 0.f;
        for (int i = 0; i < 40; i++) s += expf(z3[i] - m);
        float l = m + logf(s);
        for (int i = 0; i < 40; i++) out[i] = z3[i] - l;
    }
}

__global__ void outxp_kernel(const float* __restrict__ xs, const int* __restrict__ perm,
                             float* __restrict__ out) {
    int i = blockIdx.x * 256 + threadIdx.x;
    if (i < 1024 * HDIM) out[40 + i] = xs[i];
    else if (i < 1024 * HDIM + 1024)
        out[40 + 1024 * HDIM + (i - 1024 * HDIM)] = (float)perm[i - 1024 * HDIM];
}

__global__ void a3_kernel(const int* __restrict__ edges, float* __restrict__ out) {
    int b = blockIdx.x;
    float* row = out + (size_t)b * 1024;
    for (int i = threadIdx.x; i < 1024; i += 256) row[i] = 0.f;
    __syncthreads();
    if (threadIdx.x == 0) {
        row[b] = 1.f;
        #pragma unroll
        for (int e = 0; e < 5; e++) {
            int tgt = edges[b * 5 + e];
            if (tgt >= 0) row[tgt] = 1.f;
        }
    }
}

// ============================================================================
// Host launcher
// ============================================================================
extern "C" void kernel_launch(void* const* d_in, const int* in_sizes, int n_in,
                              void* d_out, int out_size) {
    (void)in_sizes; (void)n_in; (void)out_size;
    const float* x0  = (const float*)d_in[0];
    const float* W[3]  = {(const float*)d_in[2], (const float*)d_in[4], (const float*)d_in[6]};
    const float* bb[3] = {(const float*)d_in[3], (const float*)d_in[5], (const float*)d_in[7]};
    const float* Wp[3] = {(const float*)d_in[8], (const float*)d_in[10], (const float*)d_in[12]};
    const float* bp[3] = {(const float*)d_in[9], (const float*)d_in[11], (const float*)d_in[13]};
    const float* L1w = (const float*)d_in[14];
    const float* L1b = (const float*)d_in[15];
    const float* L2w = (const float*)d_in[16];
    const float* L2b = (const float*)d_in[17];
    const float* L3w = (const float*)d_in[18];
    const float* L3b = (const float*)d_in[19];
    float* out = (float*)d_out;

    float *p_y, *p_hA, *p_hB, *p_dinv, *p_z, *p_score, *p_sv, *p_xsb, *p_part;
    int *p_edgesb, *p_indeg, *p_idx, *p_newid, *p_permb;
    unsigned char* p_mask;
    unsigned long long* p_keys;
    cudaGetSymbolAddress((void**)&p_edgesb, g_edges);
    cudaGetSymbolAddress((void**)&p_y, g_y);
    cudaGetSymbolAddress((void**)&p_hA, g_hA);
    cudaGetSymbolAddress((void**)&p_hB, g_hB);
    cudaGetSymbolAddress((void**)&p_xsb, g_xs);
    cudaGetSymbolAddress((void**)&p_permb, g_perm);
    cudaGetSymbolAddress((void**)&p_indeg, g_indeg);
    cudaGetSymbolAddress((void**)&p_dinv, g_dinv);
    cudaGetSymbolAddress((void**)&p_z, g_z);
    cudaGetSymbolAddress((void**)&p_score, g_score);
    cudaGetSymbolAddress((void**)&p_keys, g_keys);
    cudaGetSymbolAddress((void**)&p_idx, g_idx);
    cudaGetSymbolAddress((void**)&p_sv, g_sv);
    cudaGetSymbolAddress((void**)&p_newid, g_newid);
    cudaGetSymbolAddress((void**)&p_part, g_part);
    cudaGetSymbolAddress((void**)&p_mask, g_mask);

    int* p_edges[2] = {p_edgesb, p_edgesb + NMAX * 5};
    float* p_xs[2] = {p_xsb, p_xsb + (size_t)NMAX * HDIM};
    int* p_perm[2] = {p_permb, p_permb + NMAX};

    init_kernel<<<NMAX / 256, 256>>>(p_edges[0], p_indeg);

    for (int s = 0; s < 3; s++) {
        int n = NMAX >> s;
        int k = n >> 1;
        int* ecur = p_edges[s & 1];
        int* enext = p_edges[(s + 1) & 1];
        const float* hin = (s == 0) ? x0 : p_hB;
        const float* xin = (s == 0) ? x0 : p_xs[(s - 1) & 1];
        const int* pin = (s == 0) ? nullptr : p_perm[(s - 1) & 1];

        dinvhubsmask_kernel<<<1, 1024>>>(p_indeg, ecur, p_dinv, p_mask, n);

        // feature + score pipeline (score bits == R4)
        gemmF_kernel<<<n / RPB, 256>>>(hin, W[s], bb[s], Wp[s], bp[s], p_dinv,
                                       p_y, p_hA, p_z, p_score, p_keys);
        hubpartF_kernel<<<CHUNKS, 128>>>(p_y, p_dinv, p_mask, p_part, n);
        hubfixF_kernel<<<5, 128>>>(p_part, p_dinv, bb[s], Wp[s], p_hA, p_z);
        hubfixSK_kernel<<<5, 256>>>(p_z, p_dinv, p_mask, bp[s], p_score, p_keys, n);

        // multiblock bitonic sort (+ fused extract on final pass)
        int nblk = n / CHUNK;
        sort_local_kernel<<<nblk, 1024>>>(p_keys, p_score, p_idx, p_sv,
                                          p_newid, p_indeg, k, (n == CHUNK) ? 1 : 0);
        for (int kk = 2 * CHUNK; kk <= n; kk <<= 1) {
            for (int j = kk >> 1; j >= CHUNK; j >>= 1)
                sort_cross_kernel<<<(n / 2 + 255) / 256, 256>>>(p_keys, n, kk, j);
            sort_finish_kernel<<<nblk, 1024>>>(p_keys, kk, p_score, p_idx, p_sv,
                                               p_newid, p_indeg, k,
                                               (kk == n) ? 1 : 0);
        }

        pool_kernel<<<k / 32, 128>>>(p_hA, xin, pin, ecur, p_idx, p_sv, p_newid,
                                     p_hB, p_xs[s & 1], p_perm[s & 1], enext,
                                     p_indeg, s);
    }

    mlp_kernel<<<1, 256>>>(L1w, L1b, L2w, L2b, L3w, L3b, out);
    outxp_kernel<<<(1024 * HDIM + 1024 + 255) / 256, 256>>>(p_xs[0], p_perm[0], out);
    a3_kernel<<<1024, 256>>>(p_edges[1], out + 40 + 1024 * HDIM + 1024);
}

// round 11
// speedup vs baseline: 1.2402x; 1.0447x over previous
#include <cuda_runtime.h>
#include <cstdint>

#define NMAX 8192
#define HDIM 128
#define RPB 32      // rows per gemm block == hub-partial chunk
#define CHUNK 2048  // sort chunk per block
#define MAXCH (NMAX / RPB)

// ============================================================================
// Device scratch
// ============================================================================
__device__ int   g_edges[2][NMAX * 5];
__device__ float g_hA[NMAX * HDIM];
__device__ float g_hB[NMAX * HDIM];
__device__ float g_xs[2][NMAX * HDIM];
__device__ int   g_perm[2][NMAX];
__device__ int   g_indeg[NMAX];
__device__ float g_dinv[NMAX];
__device__ float g_z[NMAX];
__device__ float g_score[NMAX];
__device__ unsigned long long g_keys[NMAX];
__device__ int   g_idx[NMAX];
__device__ float g_sv[NMAX];
__device__ int   g_newid[NMAX];
__device__ int   g_hubs[5];
__device__ int   g_nhubs;
__device__ float g_part[MAXCH * 5 * HDIM];
__device__ __align__(8) unsigned char g_mask[NMAX];
__device__ unsigned g_rmax[3][HDIM];
__device__ float g_rsum[3][HDIM];

// ============================================================================
// Helpers
// ============================================================================
__device__ __forceinline__ unsigned ordf(float v) {
    unsigned u = __float_as_uint(v);
    return (u & 0x80000000u) ? ~u : (u | 0x80000000u);
}
__device__ __forceinline__ float deco(unsigned e) {
    unsigned u = (e & 0x80000000u) ? (e & 0x7fffffffu) : ~e;
    return __uint_as_float(u);
}
__device__ __forceinline__ unsigned long long pk2(float x, float y) {
    unsigned long long r;
    asm("mov.b64 %0, {%1, %2};" : "=l"(r)
        : "r"(__float_as_uint(x)), "r"(__float_as_uint(y)));
    return r;
}
__device__ __forceinline__ void up2(unsigned long long v, float& x, float& y) {
    unsigned a, b;
    asm("mov.b64 {%0, %1}, %2;" : "=r"(a), "=r"(b) : "l"(v));
    x = __uint_as_float(a);
    y = __uint_as_float(b);
}
__device__ __forceinline__ void fma2(unsigned long long& c,
                                     unsigned long long a,
                                     unsigned long long b) {
    asm("fma.rn.f32x2 %0, %1, %2, %3;" : "=l"(c) : "l"(a), "l"(b), "l"(c));
}

// ============================================================================
// Init: degenerate stage-0 edges (eye*inf NaN semantics), closed-form indeg,
// zero readout accumulators.
// ============================================================================
__global__ void init_kernel(int* __restrict__ eout, int* __restrict__ indeg) {
    int i = blockIdx.x * 256 + threadIdx.x;
    if (i < NMAX) {
        int pos = 0;
        #pragma unroll
        for (int j = 0; j < 5; j++)
            if (j != i && pos < 4) eout[i * 5 + (pos++)] = j;
        eout[i * 5 + 4] = -1;
        indeg[i] = (i < 4) ? (NMAX - 1) : ((i == 4) ? 4 : 0);
    }
    if (i < 3 * HDIM) {
        (&g_rmax[0][0])[i] = 0u;
        (&g_rsum[0][0])[i] = 0.f;
    }
}

// ============================================================================
// dinv + hub detection + per-row mask (merged; dinv/mask bits == R4/R6)
// ============================================================================
__global__ void dinvhubsmask_kernel(const int* __restrict__ indeg,
                                    const int* __restrict__ edges,
                                    float* __restrict__ dinv,
                                    unsigned char* __restrict__ mask, int n) {
    __shared__ int cnt;
    __shared__ int sl[16];
    __shared__ int shub[5];
    int t = threadIdx.x;
    if (t == 0) cnt = 0;
    __syncthreads();
    for (int i = t; i < n; i += 1024) {
        int d = indeg[i];
        float deg = 1.f + (float)d;
        dinv[i] = 1.0f / sqrtf(deg);
        if (d > 0) {
            int p = atomicAdd(&cnt, 1);
            if (p < 16) sl[p] = i;
        }
    }
    __syncthreads();
    if (t == 0) {
        int m = cnt < 5 ? cnt : 5;
        for (int i = 1; i < m; i++) {
            int v = sl[i], j = i - 1;
            while (j >= 0 && sl[j] > v) { sl[j + 1] = sl[j]; j--; }
            sl[j + 1] = v;
        }
        g_nhubs = m;
        #pragma unroll
        for (int k = 0; k < 5; k++) {
            int v = (k < m) ? sl[k] : -1;
            g_hubs[k] = v;
            shub[k] = v;
        }
    }
    __syncthreads();
    for (int r = t; r < n; r += 1024) {
        int e0 = edges[r * 5 + 0], e1 = edges[r * 5 + 1], e2 = edges[r * 5 + 2];
        int e3 = edges[r * 5 + 3], e4 = edges[r * 5 + 4];
        unsigned m = 0;
        #pragma unroll
        for (int k = 0; k < 5; k++) {
            int hv = shub[k];
            bool hit = (hv >= 0) &&
                       (e0 == hv || e1 == hv || e2 == hv || e3 == hv || e4 == hv || r == hv);
            if (hit) m |= 1u << k;
        }
        mask[r] = (unsigned char)m;
    }
}

// ============================================================================
// Mega GEMM: y = h@W via packed fma.rn.f32x2 (lane == scalar ascending-k
// chain). hA = relu(dinv^2*y+b). Epilogue A: per-block hub partials of
// dinv*y from register accumulators (32-row chunk = low16 + high16, each an
// ascending fadd chain). Epilogue B: zdot-bit-exact z/score/keys.
// 256 threads, 32 rows/block. No y gmem traffic.
// ============================================================================
__global__ void gemmF_kernel(const float* __restrict__ h, const float* __restrict__ W,
                             const float* __restrict__ b, const float* __restrict__ Wp,
                             const float* __restrict__ bp, const float* __restrict__ dinv,
                             const unsigned char* __restrict__ mask,
                             float* __restrict__ hA, float* __restrict__ part,
                             float* __restrict__ z, float* __restrict__ score,
                             unsigned long long* __restrict__ keys) {
    __shared__ __align__(16) float sbuf[HDIM * 34];  // hs_t[k][r] -> hAs[r][c]
    __shared__ float spart[5 * HDIM];
    __shared__ float sdi[RPB];
    __shared__ float sWp[HDIM];
    const int t = threadIdx.x;
    const int c = t & 127;
    const int rb = (t >> 7) * 16;       // 0 or 16
    const int r0 = blockIdx.x * RPB;
    if (t < RPB) sdi[t] = dinv[r0 + t];
    if (t < HDIM) sWp[t] = Wp[t];
    #pragma unroll
    for (int l = 0; l < 16; l++) {
        int id = l * 256 + t;
        int rr = id >> 7, cc = id & 127;
        sbuf[cc * 34 + rr] = h[(size_t)(r0 + rr) * HDIM + cc];
    }
    __syncthreads();

    unsigned long long acc2[8];
    #pragma unroll
    for (int p = 0; p < 8; p++) acc2[p] = 0ull;
    #pragma unroll
    for (int k0 = 0; k0 < HDIM; k0 += 8) {
        float wv[8];
        #pragma unroll
        for (int q = 0; q < 8; q++) wv[q] = W[(k0 + q) * HDIM + c];
        #pragma unroll
        for (int q = 0; q < 8; q++) {
            unsigned long long w2 = pk2(wv[q], wv[q]);
            const float2* hp = (const float2*)&sbuf[(k0 + q) * 34 + rb];
            #pragma unroll
            for (int p = 0; p < 8; p++) {
                float2 h2 = hp[p];
                fma2(acc2[p], pk2(h2.x, h2.y), w2);
            }
        }
    }
    __syncthreads();   // all reads of hs_t done before overwrite

    // row masks for this thread's 16 rows (broadcast loads)
    unsigned long long um0 = *(const unsigned long long*)(mask + r0 + rb);
    unsigned long long um1 = *(const unsigned long long*)(mask + r0 + rb + 8);

    float bc = b[c];
    float hp5[5] = {0.f, 0.f, 0.f, 0.f, 0.f};
    #pragma unroll
    for (int p = 0; p < 8; p++) {
        float a0, a1;
        up2(acc2[p], a0, a1);
        int rr0 = rb + 2 * p, rr1 = rr0 + 1;
        float d0 = sdi[rr0], d1 = sdi[rr1];
        float v0 = fmaxf(fmaf(d0 * d0, a0, bc), 0.f);
        float v1 = fmaxf(fmaf(d1 * d1, a1, bc), 0.f);
        hA[(size_t)(r0 + rr0) * HDIM + c] = v0;
        hA[(size_t)(r0 + rr1) * HDIM + c] = v1;
        sbuf[rr0 * HDIM + c] = v0;
        sbuf[rr1 * HDIM + c] = v1;
        // hub partials, ascending rows (2p then 2p+1)
        unsigned long long umm = (2 * p < 8) ? um0 : um1;
        unsigned mb0 = (unsigned)(umm >> (8 * ((2 * p) & 7))) & 0xffu;
        unsigned mb1 = (unsigned)(umm >> (8 * ((2 * p + 1) & 7))) & 0xffu;
        float w0 = d0 * a0, w1 = d1 * a1;
        #pragma unroll
        for (int k = 0; k < 5; k++) {
            if ((mb0 >> k) & 1u) hp5[k] += w0;
            if ((mb1 >> k) & 1u) hp5[k] += w1;
        }
    }
    if (rb == 16) {
        #pragma unroll
        for (int k = 0; k < 5; k++) spart[k * HDIM + c] = hp5[k];
    }
    __syncthreads();   // covers sbuf hA-tile + spart
    if (rb == 0) {
        #pragma unroll
        for (int k = 0; k < 5; k++)
            part[((size_t)blockIdx.x * 5 + k) * HDIM + c] = hp5[k] + spart[k * HDIM + c];
    }

    // zdot-bit-exact epilogue: warp w handles rows w*4..w*4+3
    int w = t >> 5, lane = t & 31;
    float bp0 = bp[0];
    #pragma unroll
    for (int q = 0; q < 4; q++) {
        int rr = w * 4 + q;
        float s = 0.f;
        #pragma unroll
        for (int kk = 0; kk < 4; kk++)
            s = fmaf(sbuf[rr * HDIM + lane + 32 * kk], sWp[lane + 32 * kk], s);
        #pragma unroll
        for (int o = 16; o > 0; o >>= 1) s += __shfl_down_sync(0xffffffffu, s, o);
        if (lane == 0) {
            int r = r0 + rr;
            z[r] = s;
            float dc = sdi[rr];
            float sc = fmaf(dc * dc, s, bp0);
            score[r] = sc;
            keys[r] = ((unsigned long long)(~ordf(sc)) << 32) | (unsigned)r;
        }
    }
}

// ============================================================================
// Hub fixup: reduce nchunks partials ascending -> hub hA row -> hub z via
// zdot-bit-exact warp reduce. 5 parallel blocks.
// ============================================================================
__global__ void hubfixF_kernel(const float* __restrict__ part, int nchunks,
                               const float* __restrict__ dinv,
                               const float* __restrict__ b, const float* __restrict__ Wp,
                               float* __restrict__ hA, float* __restrict__ z) {
    int k = blockIdx.x;
    if (k >= g_nhubs) return;
    __shared__ float hv[HDIM];
    int f = threadIdx.x;
    float S = 0.f;
    for (int ch = 0; ch < nchunks; ch++) S += part[((size_t)ch * 5 + k) * HDIM + f];
    int c = g_hubs[k];
    float v = fmaf(dinv[c], S, b[f]);
    v = fmaxf(v, 0.f);
    hA[(size_t)c * HDIM + f] = v;
    hv[f] = v;
    __syncthreads();
    if (f < 32) {
        float s = 0.f;
        #pragma unroll
        for (int kk = 0; kk < 4; kk++)
            s = fmaf(hv[f + 32 * kk], Wp[f + 32 * kk], s);
        #pragma unroll
        for (int o = 16; o > 0; o >>= 1) s += __shfl_down_sync(0xffffffffu, s, o);
        if (f == 0) z[c] = s;
    }
}

// R4-verbatim hub score (5 blocks, 256 threads, strided, tree) + key pack
__global__ void hubfixSK_kernel(const float* __restrict__ z, const float* __restrict__ dinv,
                                const unsigned char* __restrict__ mask,
                                const float* __restrict__ bp,
                                float* __restrict__ score,
                                unsigned long long* __restrict__ keys, int n) {
    int k = blockIdx.x;
    if (k >= g_nhubs) return;
    int hub = g_hubs[k];
    __shared__ float red[256];
    int t = threadIdx.x;
    float p = 0.f;
    for (int r = t; r < n; r += 256) {
        if ((mask[r] >> k) & 1u) p += dinv[r] * z[r];
    }
    red[t] = p;
    __syncthreads();
    for (int o = 128; o > 0; o >>= 1) {
        if (t < o) red[t] += red[t + o];
        __syncthreads();
    }
    if (t == 0) {
        float sc = fmaf(dinv[hub], red[0], bp[0]);
        score[hub] = sc;
        keys[hub] = ((unsigned long long)(~ordf(sc)) << 32) | (unsigned)hub;
    }
}

// ============================================================================
// Multi-block bitonic sort (+ fused extract on the final pass)
// ============================================================================
__device__ __forceinline__ void do_extract2(const unsigned long long* sk, int g0, int t,
                                            const float* __restrict__ score,
                                            int* __restrict__ idx, float* __restrict__ sv,
                                            int* __restrict__ newid, int* __restrict__ indeg,
                                            int ksel) {
    #pragma unroll
    for (int h = 0; h < 2; h++) {
        int li = t + h * 1024;
        int i = g0 + li;
        int id = (int)(sk[li] & 0xffffffffull);
        newid[id] = (i < ksel) ? i : -1;
        if (i < ksel) {
            idx[i] = id;
            sv[i] = score[id];
            indeg[i] = 0;
        }
    }
}

__global__ void sort_local_kernel(unsigned long long* __restrict__ keys,
                                  const float* __restrict__ score,
                                  int* __restrict__ idx, float* __restrict__ sv,
                                  int* __restrict__ newid, int* __restrict__ indeg,
                                  int ksel, int do_ext) {
    __shared__ unsigned long long sk[CHUNK];
    int t = threadIdx.x;
    int g0 = blockIdx.x * CHUNK;
    sk[t] = keys[g0 + t];
    sk[t + 1024] = keys[g0 + t + 1024];
    __syncthreads();
    for (int k = 2; k <= CHUNK; k <<= 1) {
        for (int j = k >> 1; j > 0; j >>= 1) {
            int i = ((t / j) * 2 * j) + (t % j);
            int ixj = i + j;
            bool up = (((g0 + i) & k) == 0);
            unsigned long long a = sk[i], bb = sk[ixj];
            if ((a > bb) == up) { sk[i] = bb; sk[ixj] = a; }
            __syncthreads();
        }
    }
    keys[g0 + t] = sk[t];
    keys[g0 + t + 1024] = sk[t + 1024];
    if (do_ext) do_extract2(sk, g0, t, score, idx, sv, newid, indeg, ksel);
}

__global__ void sort_cross_kernel(unsigned long long* __restrict__ keys,
                                  int n, int k, int j) {
    int t = blockIdx.x * 256 + threadIdx.x;
    if (t >= n / 2) return;
    int i = ((t / j) * 2 * j) + (t % j);
    int ixj = i + j;
    bool up = ((i & k) == 0);
    unsigned long long a = keys[i], bb = keys[ixj];
    if ((a > bb) == up) { keys[i] = bb; keys[ixj] = a; }
}

__global__ void sort_finish_kernel(unsigned long long* __restrict__ keys, int k,
                                   const float* __restrict__ score,
                                   int* __restrict__ idx, float* __restrict__ sv,
                                   int* __restrict__ newid, int* __restrict__ indeg,
                                   int ksel, int do_ext) {
    __shared__ unsigned long long sk[CHUNK];
    int t = threadIdx.x;
    int g0 = blockIdx.x * CHUNK;
    sk[t] = keys[g0 + t];
    sk[t + 1024] = keys[g0 + t + 1024];
    __syncthreads();
    for (int j = 1024; j > 0; j >>= 1) {
        int i = ((t / j) * 2 * j) + (t % j);
        int ixj = i + j;
        bool up = (((g0 + i) & k) == 0);
        unsigned long long a = sk[i], bb = sk[ixj];
        if ((a > bb) == up) { sk[i] = bb; sk[ixj] = a; }
        __syncthreads();
    }
    keys[g0 + t] = sk[t];
    keys[g0 + t + 1024] = sk[t + 1024];
    if (do_ext) do_extract2(sk, g0, t, score, idx, sv, newid, indeg, ksel);
}

// ============================================================================
// Pool (32 new nodes/block): gather+gate h, gather xs/perm, remap edges,
// next indeg count, block-reduced readout atomics (set-invariant).
// ============================================================================
__global__ void pool_kernel(const float* __restrict__ h, const float* __restrict__ xs,
                            const int* __restrict__ perm, const int* __restrict__ edges,
                            const int* __restrict__ idx, const float* __restrict__ sv,
                            const int* __restrict__ newid,
                            float* __restrict__ h2, float* __restrict__ xs2,
                            int* __restrict__ perm2, int* __restrict__ edges2,
                            int* __restrict__ indeg, int stage) {
    __shared__ int sidx[32];
    __shared__ float sg[32];
    int c = threadIdx.x;
    int a0 = blockIdx.x * 32;
    if (c < 32) {
        sidx[c] = idx[a0 + c];
        sg[c] = tanhf(sv[a0 + c]);
    }
    __syncthreads();
    float lmax = -3.4e38f, lsum = 0.f;
    for (int rr = 0; rr < 32; rr++) {
        int a = a0 + rr;
        int o = sidx[rr];
        float v = h[(size_t)o * HDIM + c] * sg[rr];
        h2[(size_t)a * HDIM + c] = v;
        xs2[(size_t)a * HDIM + c] = xs[(size_t)o * HDIM + c];
        lmax = fmaxf(lmax, v);
        lsum += v;
        if (c < 5) {
            int e = edges[o * 5 + c];
            int ne = (e >= 0) ? newid[e] : -1;
            edges2[a * 5 + c] = ne;
            if (ne >= 0) atomicAdd(&indeg[ne], 1);
        }
        if (c == 5) perm2[a] = (perm != nullptr) ? perm[o] : o;
    }
    atomicMax(&g_rmax[stage][c], ordf(lmax));
    atomicAdd(&g_rsum[stage][c], lsum);
}

// ============================================================================
// Final MLP + log_softmax
// ============================================================================
__global__ void mlp_kernel(const float* __restrict__ L1w, const float* __restrict__ L1b,
                           const float* __restrict__ L2w, const float* __restrict__ L2b,
                           const float* __restrict__ L3w, const float* __restrict__ L3b,
                           float* __restrict__ out) {
    __shared__ float zin[256], z1[128], z2[64], z3[40];
    int t = threadIdx.x;
    if (t < 128) {
        zin[t] = deco(g_rmax[0][t]) + deco(g_rmax[1][t]) + deco(g_rmax[2][t]);
        zin[128 + t] = g_rsum[0][t] / 4096.f + g_rsum[1][t] / 2048.f + g_rsum[2][t] / 1024.f;
    }
    __syncthreads();
    if (t < 128) {
        float a = 0.f;
        for (int i = 0; i < 256; i++) a = fmaf(zin[i], L1w[i * 128 + t], a);
        z1[t] = fmaxf(a + L1b[t], 0.f);
    }
    __syncthreads();
    if (t < 64) {
        float a = 0.f;
        for (int i = 0; i < 128; i++) a = fmaf(z1[i], L2w[i * 64 + t], a);
        z2[t] = fmaxf(a + L2b[t], 0.f);
    }
    __syncthreads();
    if (t < 40) {
        float a = 0.f;
        for (int i = 0; i < 64; i++) a = fmaf(z2[i], L3w[i * 40 + t], a);
        z3[t] = a + L3b[t];
    }
    __syncthreads();
    if (t == 0) {
        float m = z3[0];
        for (int i = 1; i < 40; i++) m = fmaxf(m, z3[i]);
        float s = 0.f;
        for (int i = 0; i < 40; i++) s += expf(z3[i] - m);
        float l = m + logf(s);
        for (int i = 0; i < 40; i++) out[i] = z3[i] - l;
    }
}

__global__ void outxp_kernel(const float* __restrict__ xs, const int* __restrict__ perm,
                             float* __restrict__ out) {
    int i = blockIdx.x * 256 + threadIdx.x;
    if (i < 1024 * HDIM) out[40 + i] = xs[i];
    else if (i < 1024 * HDIM + 1024)
        out[40 + 1024 * HDIM + (i - 1024 * HDIM)] = (float)perm[i - 1024 * HDIM];
}

__global__ void a3_kernel(const int* __restrict__ edges, float* __restrict__ out) {
    int b = blockIdx.x;
    float* row = out + (size_t)b * 1024;
    for (int i = threadIdx.x; i < 1024; i += 256) row[i] = 0.f;
    __syncthreads();
    if (threadIdx.x == 0) {
        row[b] = 1.f;
        #pragma unroll
        for (int e = 0; e < 5; e++) {
            int tgt = edges[b * 5 + e];
            if (tgt >= 0) row[tgt] = 1.f;
        }
    }
}

// ============================================================================
// Host launcher
// ============================================================================
extern "C" void kernel_launch(void* const* d_in, const int* in_sizes, int n_in,
                              void* d_out, int out_size) {
    (void)in_sizes; (void)n_in; (void)out_size;
    const float* x0  = (const float*)d_in[0];
    const float* W[3]  = {(const float*)d_in[2], (const float*)d_in[4], (const float*)d_in[6]};
    const float* bb[3] = {(const float*)d_in[3], (const float*)d_in[5], (const float*)d_in[7]};
    const float* Wp[3] = {(const float*)d_in[8], (const float*)d_in[10], (const float*)d_in[12]};
    const float* bp[3] = {(const float*)d_in[9], (const float*)d_in[11], (const float*)d_in[13]};
    const float* L1w = (const float*)d_in[14];
    const float* L1b = (const float*)d_in[15];
    const float* L2w = (const float*)d_in[16];
    const float* L2b = (const float*)d_in[17];
    const float* L3w = (const float*)d_in[18];
    const float* L3b = (const float*)d_in[19];
    float* out = (float*)d_out;

    float *p_hA, *p_hB, *p_dinv, *p_z, *p_score, *p_sv, *p_xsb, *p_part;
    int *p_edgesb, *p_indeg, *p_idx, *p_newid, *p_permb;
    unsigned char* p_mask;
    unsigned long long* p_keys;
    cudaGetSymbolAddress((void**)&p_edgesb, g_edges);
    cudaGetSymbolAddress((void**)&p_hA, g_hA);
    cudaGetSymbolAddress((void**)&p_hB, g_hB);
    cudaGetSymbolAddress((void**)&p_xsb, g_xs);
    cudaGetSymbolAddress((void**)&p_permb, g_perm);
    cudaGetSymbolAddress((void**)&p_indeg, g_indeg);
    cudaGetSymbolAddress((void**)&p_dinv, g_dinv);
    cudaGetSymbolAddress((void**)&p_z, g_z);
    cudaGetSymbolAddress((void**)&p_score, g_score);
    cudaGetSymbolAddress((void**)&p_keys, g_keys);
    cudaGetSymbolAddress((void**)&p_idx, g_idx);
    cudaGetSymbolAddress((void**)&p_sv, g_sv);
    cudaGetSymbolAddress((void**)&p_newid, g_newid);
    cudaGetSymbolAddress((void**)&p_part, g_part);
    cudaGetSymbolAddress((void**)&p_mask, g_mask);

    int* p_edges[2] = {p_edgesb, p_edgesb + NMAX * 5};
    float* p_xs[2] = {p_xsb, p_xsb + (size_t)NMAX * HDIM};
    int* p_perm[2] = {p_permb, p_permb + NMAX};

    init_kernel<<<NMAX / 256, 256>>>(p_edges[0], p_indeg);

    for (int s = 0; s < 3; s++) {
        int n = NMAX >> s;
        int k = n >> 1;
        int nchunks = n / RPB;
        int* ecur = p_edges[s & 1];
        int* enext = p_edges[(s + 1) & 1];
        const float* hin = (s == 0) ? x0 : p_hB;
        const float* xin = (s == 0) ? x0 : p_xs[(s - 1) & 1];
        const int* pin = (s == 0) ? nullptr : p_perm[(s - 1) & 1];

        dinvhubsmask_kernel<<<1, 1024>>>(p_indeg, ecur, p_dinv, p_mask, n);

        // feature + score pipeline (non-hub score bits == R4 lineage)
        gemmF_kernel<<<nchunks, 256>>>(hin, W[s], bb[s], Wp[s], bp[s], p_dinv,
                                       p_mask, p_hA, p_part, p_z, p_score, p_keys);
        hubfixF_kernel<<<5, 128>>>(p_part, nchunks, p_dinv, bb[s], Wp[s], p_hA, p_z);
        hubfixSK_kernel<<<5, 256>>>(p_z, p_dinv, p_mask, bp[s], p_score, p_keys, n);

        // multiblock bitonic sort (+ fused extract on final pass)
        int nblk = n / CHUNK;
        sort_local_kernel<<<nblk, 1024>>>(p_keys, p_score, p_idx, p_sv,
                                          p_newid, p_indeg, k, (n == CHUNK) ? 1 : 0);
        for (int kk = 2 * CHUNK; kk <= n; kk <<= 1) {
            for (int j = kk >> 1; j >= CHUNK; j >>= 1)
                sort_cross_kernel<<<(n / 2 + 255) / 256, 256>>>(p_keys, n, kk, j);
            sort_finish_kernel<<<nblk, 1024>>>(p_keys, kk, p_score, p_idx, p_sv,
                                               p_newid, p_indeg, k,
                                               (kk == n) ? 1 : 0);
        }

        pool_kernel<<<k / 32, 128>>>(p_hA, xin, pin, ecur, p_idx, p_sv, p_newid,
                                     p_hB, p_xs[s & 1], p_perm[s & 1], enext,
                                     p_indeg, s);
    }

    mlp_kernel<<<1, 256>>>(L1w, L1b, L2w, L2b, L3w, L3b, out);
    outxp_kernel<<<(1024 * HDIM + 1024 + 255) / 256, 256>>>(p_xs[0], p_perm[0], out);
    a3_kernel<<<1024, 256>>>(p_edges[1], out + 40 + 1024 * HDIM + 1024);
}